// round 11
// baseline (speedup 1.0000x reference)
#include <cuda_runtime.h>
#include <cuda_fp16.h>
#include <math.h>
#include <stdint.h>

// Problem constants
#define Bq  2
#define Sq  2048
#define Dm  1024
#define Hh  16
#define HDc 64
#define Mtot (Bq*Sq)   // 4096

// ---------------- device scratch (fp16) ----------------
__device__ __half g_Xh[Mtot*Dm], g_Xl[Mtot*Dm];   // x split hi/lo
__device__ __half g_Wf[4][Dm*Dm];                 // W^T single fp16, [N][K]
__device__ __half g_Qh[Mtot*Dm], g_Ql[Mtot*Dm];   // Q split, pre-scaled 0.125*log2e
__device__ __half g_Kf[Mtot*Dm], g_Vf[Mtot*Dm];   // K/V single
__device__ __half g_AH[Mtot*Dm], g_AL[Mtot*Dm];   // attention out split

// ---------------- helpers ----------------
__device__ __forceinline__ uint32_t smem_u32(const void* p) {
    uint32_t a;
    asm("{ .reg .u64 t; cvta.to.shared.u64 t, %1; cvt.u32.u64 %0, t; }" : "=r"(a) : "l"(p));
    return a;
}
__device__ __forceinline__ void cp16(uint32_t saddr, const void* gptr) {
    asm volatile("cp.async.cg.shared.global [%0], [%1], 16;" :: "r"(saddr), "l"(gptr) : "memory");
}
__device__ __forceinline__ void cp_commit() {
    asm volatile("cp.async.commit_group;" ::: "memory");
}
__device__ __forceinline__ void cp_wait0() {
    asm volatile("cp.async.wait_group 0;" ::: "memory");
}
__device__ __forceinline__ void ldsm_x4(uint32_t* r, uint32_t a) {
    asm volatile("ldmatrix.sync.aligned.m8n8.x4.shared.b16 {%0,%1,%2,%3}, [%4];"
                 : "=r"(r[0]), "=r"(r[1]), "=r"(r[2]), "=r"(r[3]) : "r"(a));
}
__device__ __forceinline__ void ldsm_x2(uint32_t* r, uint32_t a) {
    asm volatile("ldmatrix.sync.aligned.m8n8.x2.shared.b16 {%0,%1}, [%2];"
                 : "=r"(r[0]), "=r"(r[1]) : "r"(a));
}
__device__ __forceinline__ void ldsm_x2t(uint32_t* r, uint32_t a) {
    asm volatile("ldmatrix.sync.aligned.m8n8.x2.trans.shared.b16 {%0,%1}, [%2];"
                 : "=r"(r[0]), "=r"(r[1]) : "r"(a));
}
__device__ __forceinline__ void mma16816(float* c, const uint32_t* a, const uint32_t* b) {
    asm volatile(
        "mma.sync.aligned.m16n8k16.row.col.f32.f16.f16.f32 "
        "{%0,%1,%2,%3}, {%4,%5,%6,%7}, {%8,%9}, {%0,%1,%2,%3};"
        : "+f"(c[0]), "+f"(c[1]), "+f"(c[2]), "+f"(c[3])
        : "r"(a[0]), "r"(a[1]), "r"(a[2]), "r"(a[3]), "r"(b[0]), "r"(b[1]));
}
__device__ __forceinline__ float ex2f(float x) {
    float y;
    asm("ex2.approx.f32 %0, %1;" : "=f"(y) : "f"(x));
    return y;
}
__device__ __forceinline__ uint32_t h2pack(float a, float b) {
    __half2 h = __floats2half2_rn(a, b);
    return *(uint32_t*)&h;
}
__device__ __forceinline__ uint32_t h2split(float a, float b, uint32_t& lo) {
    __half ha = __float2half_rn(a), hb = __float2half_rn(b);
    __half la = __float2half_rn(a - __half2float(ha));
    __half lb = __float2half_rn(b - __half2float(hb));
    uint16_t uha = *(uint16_t*)&ha, uhb = *(uint16_t*)&hb;
    uint16_t ula = *(uint16_t*)&la, ulb = *(uint16_t*)&lb;
    lo = (uint32_t)ula | ((uint32_t)ulb << 16);
    return (uint32_t)uha | ((uint32_t)uhb << 16);
}

// ---------------------------------------------------------------------------
// conversion kernels
// ---------------------------------------------------------------------------
__global__ __launch_bounds__(256) void convx_k(const float* __restrict__ X,
                                               __half* __restrict__ H,
                                               __half* __restrict__ L)
{
    int i = blockIdx.x * blockDim.x + threadIdx.x;
    float4 v = ((const float4*)X)[i];
    uint32_t l0, l1;
    uint32_t h0 = h2split(v.x, v.y, l0);
    uint32_t h1 = h2split(v.z, v.w, l1);
    ((uint2*)H)[i] = make_uint2(h0, h1);
    ((uint2*)L)[i] = make_uint2(l0, l1);
}

__global__ __launch_bounds__(256) void convw_k(const float* __restrict__ W0,
                                               const float* __restrict__ W1,
                                               const float* __restrict__ W2,
                                               const float* __restrict__ W3,
                                               __half* __restrict__ T)
{
    __shared__ float t[32][33];
    const int z = blockIdx.z;
    const float* W = z == 0 ? W0 : (z == 1 ? W1 : (z == 2 ? W2 : W3));
    __half* th = T + (size_t)z * Dm * Dm;
    int n0 = blockIdx.x * 32, k0 = blockIdx.y * 32;
    int tx = threadIdx.x, ty = threadIdx.y;
    #pragma unroll
    for (int j = ty; j < 32; j += 8)
        t[j][tx] = W[(size_t)(k0 + j) * Dm + n0 + tx];
    __syncthreads();
    #pragma unroll
    for (int j = ty; j < 32; j += 8)
        th[(size_t)(n0 + j) * Dm + k0 + tx] = __float2half_rn(t[tx][j]);
}

// ---------------------------------------------------------------------------
// GEMM core (R8): CTA 128x128, 4 warps (64x64), BK=32, 2-stage pipeline.
// ---------------------------------------------------------------------------
#define GP 40
#define MATB (128*GP*2)   // 10240
#define STAGEB (3*MATB)   // 30720

__device__ __forceinline__ void gemm_core(
    const uint32_t sb,
    const __half* __restrict__ gAh, const __half* __restrict__ gAl,
    const __half* __restrict__ gB,
    int tid, int lane, int wr, int wc, float acc[4][8][4])
{
    auto issue = [&](int kt, int buf) {
        const int kc = kt * 32;
        const uint32_t base = sb + buf * STAGEB;
        #pragma unroll
        for (int p = 0; p < 4; p++) {
            int i = tid + p * 128;
            int r = i >> 2, c = i & 3;
            uint32_t so = (uint32_t)(r * (GP*2) + c * 16);
            size_t go = (size_t)r * Dm + kc + c * 8;
            cp16(base + 0*MATB + so, gAh + go);
            cp16(base + 1*MATB + so, gAl + go);
            cp16(base + 2*MATB + so, gB  + go);
        }
        cp_commit();
    };

    const int aRow = wr * 64 + (lane & 15);
    const int aKh  = (lane >> 4) * 8;
    const int bRow = wc * 64 + (lane & 7);
    const int bKh  = ((lane >> 3) & 1) * 8;

    issue(0, 0);

    for (int kt = 0; kt < 32; kt++) {
        cp_wait0();
        __syncthreads();
        if (kt + 1 < 32) issue(kt + 1, (kt + 1) & 1);

        const uint32_t base = sb + (kt & 1) * STAGEB;
        #pragma unroll
        for (int kk = 0; kk < 2; kk++) {
            uint32_t bf[8][2];
            #pragma unroll
            for (int j = 0; j < 8; j++) {
                uint32_t ba = base + 2*MATB +
                    (uint32_t)(((bRow + j * 8) * GP + kk * 16 + bKh) * 2);
                ldsm_x2(bf[j], ba);
            }
            #pragma unroll
            for (int t = 0; t < 4; t++) {
                uint32_t aa = base +
                    (uint32_t)(((aRow + t * 16) * GP + kk * 16 + aKh) * 2);
                uint32_t ah[4], al[4];
                ldsm_x4(ah, aa);
                ldsm_x4(al, aa + MATB);
                #pragma unroll
                for (int j = 0; j < 8; j++) {
                    mma16816(acc[t][j], ah, bf[j]);
                    mma16816(acc[t][j], al, bf[j]);
                }
            }
        }
    }
}

// Fused QKV projection: C[4096][3072] = X @ [WQ|WK|WV]^T
__global__ __launch_bounds__(128) void qkv_gemm(
    const __half* __restrict__ Agh, const __half* __restrict__ Agl,
    const __half* __restrict__ Bg,
    __half* __restrict__ Qh, __half* __restrict__ Ql,
    __half* __restrict__ Kf, __half* __restrict__ Vf)
{
    extern __shared__ char smc[];
    const uint32_t sb = smem_u32(smc);
    const int tid = threadIdx.x, lane = tid & 31, w = tid >> 5;
    const int wr = w >> 1, wc = w & 1;
    const int rowBase = blockIdx.y * 128, colBase = blockIdx.x * 128;

    float acc[4][8][4];
    #pragma unroll
    for (int t = 0; t < 4; t++)
        #pragma unroll
        for (int j = 0; j < 8; j++)
            #pragma unroll
            for (int e = 0; e < 4; e++) acc[t][j][e] = 0.f;

    gemm_core(sb, Agh + (size_t)rowBase * Dm, Agl + (size_t)rowBase * Dm,
              Bg + (size_t)colBase * Dm, tid, lane, wr, wc, acc);

    const int er = lane >> 2, ec = (lane & 3) * 2;
    const int which = colBase >> 10;            // 0=Q 1=K 2=V
    const float scale = which == 0 ? 0.125f * 1.4426950408889634f : 1.0f;
    #pragma unroll
    for (int t = 0; t < 4; t++) {
        #pragma unroll
        for (int j = 0; j < 8; j++) {
            int m0 = rowBase + wr * 64 + t * 16 + er;
            int n  = (colBase & 1023) + wc * 64 + j * 8 + ec;
            int h = n >> 6, hd = n & 63;
            #pragma unroll
            for (int half = 0; half < 2; half++) {
                int m = m0 + half * 8;
                int b = m >> 11, s = m & 2047;
                size_t o = ((size_t)((b * Hh + h) * Sq + s)) * HDc + hd;
                float v0 = acc[t][j][2*half] * scale, v1 = acc[t][j][2*half+1] * scale;
                if (which == 0) {
                    uint32_t lo;
                    uint32_t hi = h2split(v0, v1, lo);
                    *(uint32_t*)&Qh[o] = hi;
                    *(uint32_t*)&Ql[o] = lo;
                } else {
                    __half* d = which == 1 ? Kf : Vf;
                    *(uint32_t*)&d[o] = h2pack(v0, v1);
                }
            }
        }
    }
}

// Output projection: C[4096][1024] fp32 = AH/AL @ WO^T
__global__ __launch_bounds__(128) void wo_gemm(
    const __half* __restrict__ Agh, const __half* __restrict__ Agl,
    const __half* __restrict__ Bg, float* __restrict__ dst)
{
    extern __shared__ char smc[];
    const uint32_t sb = smem_u32(smc);
    const int tid = threadIdx.x, lane = tid & 31, w = tid >> 5;
    const int wr = w >> 1, wc = w & 1;
    const int rowBase = blockIdx.y * 128, colBase = blockIdx.x * 128;

    float acc[4][8][4];
    #pragma unroll
    for (int t = 0; t < 4; t++)
        #pragma unroll
        for (int j = 0; j < 8; j++)
            #pragma unroll
            for (int e = 0; e < 4; e++) acc[t][j][e] = 0.f;

    gemm_core(sb, Agh + (size_t)rowBase * Dm, Agl + (size_t)rowBase * Dm,
              Bg + (size_t)colBase * Dm, tid, lane, wr, wc, acc);

    const int er = lane >> 2, ec = (lane & 3) * 2;
    #pragma unroll
    for (int t = 0; t < 4; t++) {
        #pragma unroll
        for (int j = 0; j < 8; j++) {
            int m0 = rowBase + wr * 64 + t * 16 + er;
            int n  = colBase + wc * 64 + j * 8 + ec;
            *(float2*)&dst[(size_t)m0 * Dm + n] = make_float2(acc[t][j][0], acc[t][j][1]);
            *(float2*)&dst[(size_t)(m0 + 8) * Dm + n] = make_float2(acc[t][j][2], acc[t][j][3]);
        }
    }
}

// ---------------------------------------------------------------------------
// HMMA flash attention (R8, best measured): 256 thr, 8 warps x 16 q-rows,
// 64-key tiles, 2-stage cp.async. QK: 2 MMA (Q split), PV: 1 MMA.
// ---------------------------------------------------------------------------
#define AP 72
#define KTB (64*AP*2)      // 9216
#define QTB (128*AP*2)     // 18432
#define QB  (2*QTB)        // 36864
#define STG (2*KTB)        // 18432 (K, V)
#define ASMEM (QB + 2*STG) // 73728

__global__ __launch_bounds__(256) void attn_mma(
    const __half* __restrict__ Qhg, const __half* __restrict__ Qlg,
    const __half* __restrict__ Kfg, const __half* __restrict__ Vfg,
    __half* __restrict__ AH, __half* __restrict__ AL)
{
    extern __shared__ char smc[];
    const uint32_t sb = smem_u32(smc);
    const uint32_t sQh = sb, sQl = sb + QTB;

    const int tid = threadIdx.x, lane = tid & 31, w = tid >> 5;
    const int q0 = ((int)gridDim.x - 1 - (int)blockIdx.x) * 128;  // longest-first
    const int h  = blockIdx.y;
    const int b  = blockIdx.z;

    const size_t hb = (size_t)((b * Hh + h) * Sq) * HDc;
    const __half* Qhb = Qhg + hb;
    const __half* Qlb = Qlg + hb;
    const __half* Kfb = Kfg + hb;
    const __half* Vfb = Vfg + hb;

    for (int i = tid; i < 1024; i += 256) {
        int r = i >> 3, c = (i & 7) * 8;
        uint32_t off = (uint32_t)(r * AP + c) * 2;
        *(uint4*)(smc + off)       = *(const uint4*)&Qhb[(size_t)(q0 + r) * HDc + c];
        *(uint4*)(smc + QTB + off) = *(const uint4*)&Qlb[(size_t)(q0 + r) * HDc + c];
    }

    const int nTiles = q0 / 64 + 2;

    auto issue = [&](int kt, int st) {
        const uint32_t base = sb + QB + st * STG;
        #pragma unroll
        for (int p = 0; p < 2; p++) {
            int i = tid + p * 256;
            int r = i >> 3, c = (i & 7) * 8;
            uint32_t so = (uint32_t)(r * AP + c) * 2;
            size_t go = (size_t)(kt * 64 + r) * HDc + c;
            cp16(base + so, Kfb + go);
            cp16(base + KTB + so, Vfb + go);
        }
        cp_commit();
    };

    float m0 = -INFINITY, m1 = -INFINITY, l0s = 0.f, l1s = 0.f;
    float o[8][4];
    #pragma unroll
    for (int j = 0; j < 8; j++)
        #pragma unroll
        for (int e = 0; e < 4; e++) o[j][e] = 0.f;

    const int er = lane >> 2, ec = (lane & 3) * 2;
    const int wrow = q0 + w * 16;

    issue(0, 0);

    for (int kt = 0; kt < nTiles; kt++) {
        cp_wait0();
        __syncthreads();
        if (kt + 1 < nTiles) issue(kt + 1, (kt + 1) & 1);

        if (kt * 64 <= wrow + 15) {
            const uint32_t base = sb + QB + (kt & 1) * STG;
            const uint32_t sK = base, sV = base + KTB;

            float s[8][4];
            #pragma unroll
            for (int j = 0; j < 8; j++)
                #pragma unroll
                for (int e = 0; e < 4; e++) s[j][e] = 0.f;

            #pragma unroll
            for (int ks = 0; ks < 4; ks++) {
                uint32_t aoff = (uint32_t)(((w * 16 + (lane & 15)) * AP + ks * 16 + (lane >> 4) * 8) * 2);
                uint32_t qh[4], ql[4];
                ldsm_x4(qh, sQh + aoff);
                ldsm_x4(ql, sQl + aoff);
                #pragma unroll
                for (int j = 0; j < 8; j++) {
                    uint32_t boff = (uint32_t)(((j * 8 + (lane & 7)) * AP + ks * 16 + ((lane >> 3) & 1) * 8) * 2);
                    uint32_t kf[2];
                    ldsm_x2(kf, sK + boff);
                    mma16816(s[j], qh, kf);
                    mma16816(s[j], ql, kf);
                }
            }

            const int row0 = wrow + er, row1 = row0 + 8;
            if (kt * 64 + 63 > row0) {
                #pragma unroll
                for (int j = 0; j < 8; j++) {
                    int k = kt * 64 + j * 8 + ec;
                    if (k     > row0) s[j][0] = -INFINITY;
                    if (k + 1 > row0) s[j][1] = -INFINITY;
                    if (k     > row1) s[j][2] = -INFINITY;
                    if (k + 1 > row1) s[j][3] = -INFINITY;
                }
            }

            float rm0 = -INFINITY, rm1 = -INFINITY;
            #pragma unroll
            for (int j = 0; j < 8; j++) {
                rm0 = fmaxf(rm0, fmaxf(s[j][0], s[j][1]));
                rm1 = fmaxf(rm1, fmaxf(s[j][2], s[j][3]));
            }
            rm0 = fmaxf(rm0, __shfl_xor_sync(0xffffffffu, rm0, 1));
            rm0 = fmaxf(rm0, __shfl_xor_sync(0xffffffffu, rm0, 2));
            rm1 = fmaxf(rm1, __shfl_xor_sync(0xffffffffu, rm1, 1));
            rm1 = fmaxf(rm1, __shfl_xor_sync(0xffffffffu, rm1, 2));
            float mn0 = fmaxf(m0, rm0), mn1 = fmaxf(m1, rm1);
            float c0 = ex2f(m0 - mn0), c1 = ex2f(m1 - mn1);
            m0 = mn0; m1 = mn1;

            float la0 = 0.f, la1 = 0.f;
            #pragma unroll
            for (int j = 0; j < 8; j++) {
                s[j][0] = ex2f(s[j][0] - m0);
                s[j][1] = ex2f(s[j][1] - m0);
                s[j][2] = ex2f(s[j][2] - m1);
                s[j][3] = ex2f(s[j][3] - m1);
                la0 += s[j][0] + s[j][1];
                la1 += s[j][2] + s[j][3];
                o[j][0] *= c0; o[j][1] *= c0;
                o[j][2] *= c1; o[j][3] *= c1;
            }
            l0s = l0s * c0 + la0;
            l1s = l1s * c1 + la1;

            #pragma unroll
            for (int aj = 0; aj < 4; aj++) {
                uint32_t pp[4];
                pp[0] = h2pack(s[2*aj][0],   s[2*aj][1]);
                pp[1] = h2pack(s[2*aj][2],   s[2*aj][3]);
                pp[2] = h2pack(s[2*aj+1][0], s[2*aj+1][1]);
                pp[3] = h2pack(s[2*aj+1][2], s[2*aj+1][3]);
                #pragma unroll
                for (int j = 0; j < 8; j++) {
                    uint32_t voff = (uint32_t)(((aj * 16 + (lane & 7) + ((lane >> 3) & 1) * 8) * AP + j * 8) * 2);
                    uint32_t vf[2];
                    ldsm_x2t(vf, sV + voff);
                    mma16816(o[j], pp, vf);
                }
            }
        }
    }

    l0s += __shfl_xor_sync(0xffffffffu, l0s, 1);
    l0s += __shfl_xor_sync(0xffffffffu, l0s, 2);
    l1s += __shfl_xor_sync(0xffffffffu, l1s, 1);
    l1s += __shfl_xor_sync(0xffffffffu, l1s, 2);
    float i0 = 1.f / l0s, i1 = 1.f / l1s;

    const int row0 = wrow + er;
    #pragma unroll
    for (int j = 0; j < 8; j++) {
        int dim = j * 8 + ec;
        size_t o0 = (size_t)(b * Sq + row0) * Dm + h * HDc + dim;
        size_t o1 = (size_t)(b * Sq + row0 + 8) * Dm + h * HDc + dim;
        uint32_t lo;
        uint32_t hi = h2split(o[j][0] * i0, o[j][1] * i0, lo);
        *(uint32_t*)&AH[o0] = hi; *(uint32_t*)&AL[o0] = lo;
        hi = h2split(o[j][2] * i1, o[j][3] * i1, lo);
        *(uint32_t*)&AH[o1] = hi; *(uint32_t*)&AL[o1] = lo;
    }
}

// ---------------------------------------------------------------------------
extern "C" void kernel_launch(void* const* d_in, const int* in_sizes, int n_in,
                              void* d_out, int out_size)
{
    (void)in_sizes; (void)n_in; (void)out_size;
    const float* x  = (const float*)d_in[0];
    const float* WQ = (const float*)d_in[1];
    const float* WK = (const float*)d_in[2];
    const float* WV = (const float*)d_in[3];
    const float* WO = (const float*)d_in[4];
    float* out = (float*)d_out;

    __half *xh, *xl, *wf, *ah, *al, *qh, *ql, *kf, *vf;
    cudaGetSymbolAddress((void**)&xh, g_Xh);
    cudaGetSymbolAddress((void**)&xl, g_Xl);
    cudaGetSymbolAddress((void**)&wf, g_Wf);
    cudaGetSymbolAddress((void**)&ah, g_AH);
    cudaGetSymbolAddress((void**)&al, g_AL);
    cudaGetSymbolAddress((void**)&qh, g_Qh);
    cudaGetSymbolAddress((void**)&ql, g_Ql);
    cudaGetSymbolAddress((void**)&kf, g_Kf);
    cudaGetSymbolAddress((void**)&vf, g_Vf);

    static int attrs_set = 0;
    int gsmem = 2 * STAGEB;        // 61440
    int asmem = ASMEM;             // 73728
    if (!attrs_set) {
        cudaFuncSetAttribute(qkv_gemm, cudaFuncAttributeMaxDynamicSharedMemorySize, gsmem);
        cudaFuncSetAttribute(wo_gemm,  cudaFuncAttributeMaxDynamicSharedMemorySize, gsmem);
        cudaFuncSetAttribute(attn_mma, cudaFuncAttributeMaxDynamicSharedMemorySize, asmem);
        attrs_set = 1;
    }

    convx_k<<<Mtot * Dm / 4 / 256, 256>>>(x, xh, xl);
    convw_k<<<dim3(32, 32, 4), dim3(32, 8)>>>(WQ, WK, WV, WO, wf);

    qkv_gemm<<<dim3(3 * Dm / 128, Mtot / 128), 128, gsmem>>>(
        xh, xl, wf, qh, ql, kf, vf);

    attn_mma<<<dim3(Sq / 128, Hh, Bq), 256, asmem>>>(qh, ql, kf, vf, ah, al);

    wo_gemm<<<dim3(Dm / 128, Mtot / 128), 128, gsmem>>>(
        ah, al, wf + 3 * (size_t)Dm * Dm, out);
}

// round 12
// speedup vs baseline: 1.0358x; 1.0358x over previous
#include <cuda_runtime.h>
#include <cuda_fp16.h>
#include <math.h>
#include <stdint.h>

// Problem constants
#define Bq  2
#define Sq  2048
#define Dm  1024
#define Hh  16
#define HDc 64
#define Mtot (Bq*Sq)   // 4096

// ---------------- device scratch (fp16) ----------------
__device__ __half g_Xh[Mtot*Dm], g_Xl[Mtot*Dm];   // x split hi/lo
__device__ __half g_Wf[4][Dm*Dm];                 // W^T single fp16, [N][K]
__device__ __half g_Qh[Mtot*Dm], g_Ql[Mtot*Dm];   // Q split, pre-scaled 0.125*log2e
__device__ __half g_Kf[Mtot*Dm], g_Vf[Mtot*Dm];   // K/V single
__device__ __half g_AH[Mtot*Dm], g_AL[Mtot*Dm];   // attention out split

// ---------------- helpers ----------------
__device__ __forceinline__ uint32_t smem_u32(const void* p) {
    uint32_t a;
    asm("{ .reg .u64 t; cvta.to.shared.u64 t, %1; cvt.u32.u64 %0, t; }" : "=r"(a) : "l"(p));
    return a;
}
__device__ __forceinline__ void cp16(uint32_t saddr, const void* gptr) {
    asm volatile("cp.async.cg.shared.global [%0], [%1], 16;" :: "r"(saddr), "l"(gptr) : "memory");
}
__device__ __forceinline__ void cp_commit() {
    asm volatile("cp.async.commit_group;" ::: "memory");
}
__device__ __forceinline__ void cp_wait0() {
    asm volatile("cp.async.wait_group 0;" ::: "memory");
}
__device__ __forceinline__ void ldsm_x4(uint32_t* r, uint32_t a) {
    asm volatile("ldmatrix.sync.aligned.m8n8.x4.shared.b16 {%0,%1,%2,%3}, [%4];"
                 : "=r"(r[0]), "=r"(r[1]), "=r"(r[2]), "=r"(r[3]) : "r"(a));
}
__device__ __forceinline__ void ldsm_x2(uint32_t* r, uint32_t a) {
    asm volatile("ldmatrix.sync.aligned.m8n8.x2.shared.b16 {%0,%1}, [%2];"
                 : "=r"(r[0]), "=r"(r[1]) : "r"(a));
}
__device__ __forceinline__ void ldsm_x2t(uint32_t* r, uint32_t a) {
    asm volatile("ldmatrix.sync.aligned.m8n8.x2.trans.shared.b16 {%0,%1}, [%2];"
                 : "=r"(r[0]), "=r"(r[1]) : "r"(a));
}
__device__ __forceinline__ void mma16816(float* c, const uint32_t* a, const uint32_t* b) {
    asm volatile(
        "mma.sync.aligned.m16n8k16.row.col.f32.f16.f16.f32 "
        "{%0,%1,%2,%3}, {%4,%5,%6,%7}, {%8,%9}, {%0,%1,%2,%3};"
        : "+f"(c[0]), "+f"(c[1]), "+f"(c[2]), "+f"(c[3])
        : "r"(a[0]), "r"(a[1]), "r"(a[2]), "r"(a[3]), "r"(b[0]), "r"(b[1]));
}
__device__ __forceinline__ float ex2f(float x) {
    float y;
    asm("ex2.approx.f32 %0, %1;" : "=f"(y) : "f"(x));
    return y;
}
__device__ __forceinline__ uint32_t ex2h2(uint32_t x) {
    uint32_t y;
    asm("ex2.approx.f16x2 %0, %1;" : "=r"(y) : "r"(x));
    return y;
}
__device__ __forceinline__ uint32_t h2pack(float a, float b) {
    __half2 h = __floats2half2_rn(a, b);
    return *(uint32_t*)&h;
}
__device__ __forceinline__ uint32_t h2split(float a, float b, uint32_t& lo) {
    __half ha = __float2half_rn(a), hb = __float2half_rn(b);
    __half la = __float2half_rn(a - __half2float(ha));
    __half lb = __float2half_rn(b - __half2float(hb));
    uint16_t uha = *(uint16_t*)&ha, uhb = *(uint16_t*)&hb;
    uint16_t ula = *(uint16_t*)&la, ulb = *(uint16_t*)&lb;
    lo = (uint32_t)ula | ((uint32_t)ulb << 16);
    return (uint32_t)uha | ((uint32_t)uhb << 16);
}

// ---------------------------------------------------------------------------
// conversion kernels
// ---------------------------------------------------------------------------
__global__ __launch_bounds__(256) void convx_k(const float* __restrict__ X,
                                               __half* __restrict__ H,
                                               __half* __restrict__ L)
{
    int i = blockIdx.x * blockDim.x + threadIdx.x;
    float4 v = ((const float4*)X)[i];
    uint32_t l0, l1;
    uint32_t h0 = h2split(v.x, v.y, l0);
    uint32_t h1 = h2split(v.z, v.w, l1);
    ((uint2*)H)[i] = make_uint2(h0, h1);
    ((uint2*)L)[i] = make_uint2(l0, l1);
}

__global__ __launch_bounds__(256) void convw_k(const float* __restrict__ W0,
                                               const float* __restrict__ W1,
                                               const float* __restrict__ W2,
                                               const float* __restrict__ W3,
                                               __half* __restrict__ T)
{
    __shared__ float t[32][33];
    const int z = blockIdx.z;
    const float* W = z == 0 ? W0 : (z == 1 ? W1 : (z == 2 ? W2 : W3));
    __half* th = T + (size_t)z * Dm * Dm;
    int n0 = blockIdx.x * 32, k0 = blockIdx.y * 32;
    int tx = threadIdx.x, ty = threadIdx.y;
    #pragma unroll
    for (int j = ty; j < 32; j += 8)
        t[j][tx] = W[(size_t)(k0 + j) * Dm + n0 + tx];
    __syncthreads();
    #pragma unroll
    for (int j = ty; j < 32; j += 8)
        th[(size_t)(n0 + j) * Dm + k0 + tx] = __float2half_rn(t[tx][j]);
}

// ---------------------------------------------------------------------------
// GEMM core (R8): CTA 128x128, 4 warps (64x64), BK=32, 2-stage pipeline.
// ---------------------------------------------------------------------------
#define GP 40
#define MATB (128*GP*2)   // 10240
#define STAGEB (3*MATB)   // 30720

__device__ __forceinline__ void gemm_core(
    const uint32_t sb,
    const __half* __restrict__ gAh, const __half* __restrict__ gAl,
    const __half* __restrict__ gB,
    int tid, int lane, int wr, int wc, float acc[4][8][4])
{
    auto issue = [&](int kt, int buf) {
        const int kc = kt * 32;
        const uint32_t base = sb + buf * STAGEB;
        #pragma unroll
        for (int p = 0; p < 4; p++) {
            int i = tid + p * 128;
            int r = i >> 2, c = i & 3;
            uint32_t so = (uint32_t)(r * (GP*2) + c * 16);
            size_t go = (size_t)r * Dm + kc + c * 8;
            cp16(base + 0*MATB + so, gAh + go);
            cp16(base + 1*MATB + so, gAl + go);
            cp16(base + 2*MATB + so, gB  + go);
        }
        cp_commit();
    };

    const int aRow = wr * 64 + (lane & 15);
    const int aKh  = (lane >> 4) * 8;
    const int bRow = wc * 64 + (lane & 7);
    const int bKh  = ((lane >> 3) & 1) * 8;

    issue(0, 0);

    for (int kt = 0; kt < 32; kt++) {
        cp_wait0();
        __syncthreads();
        if (kt + 1 < 32) issue(kt + 1, (kt + 1) & 1);

        const uint32_t base = sb + (kt & 1) * STAGEB;
        #pragma unroll
        for (int kk = 0; kk < 2; kk++) {
            uint32_t bf[8][2];
            #pragma unroll
            for (int j = 0; j < 8; j++) {
                uint32_t ba = base + 2*MATB +
                    (uint32_t)(((bRow + j * 8) * GP + kk * 16 + bKh) * 2);
                ldsm_x2(bf[j], ba);
            }
            #pragma unroll
            for (int t = 0; t < 4; t++) {
                uint32_t aa = base +
                    (uint32_t)(((aRow + t * 16) * GP + kk * 16 + aKh) * 2);
                uint32_t ah[4], al[4];
                ldsm_x4(ah, aa);
                ldsm_x4(al, aa + MATB);
                #pragma unroll
                for (int j = 0; j < 8; j++) {
                    mma16816(acc[t][j], ah, bf[j]);
                    mma16816(acc[t][j], al, bf[j]);
                }
            }
        }
    }
}

// Fused QKV projection: C[4096][3072] = X @ [WQ|WK|WV]^T
__global__ __launch_bounds__(128) void qkv_gemm(
    const __half* __restrict__ Agh, const __half* __restrict__ Agl,
    const __half* __restrict__ Bg,
    __half* __restrict__ Qh, __half* __restrict__ Ql,
    __half* __restrict__ Kf, __half* __restrict__ Vf)
{
    extern __shared__ char smc[];
    const uint32_t sb = smem_u32(smc);
    const int tid = threadIdx.x, lane = tid & 31, w = tid >> 5;
    const int wr = w >> 1, wc = w & 1;
    const int rowBase = blockIdx.y * 128, colBase = blockIdx.x * 128;

    float acc[4][8][4];
    #pragma unroll
    for (int t = 0; t < 4; t++)
        #pragma unroll
        for (int j = 0; j < 8; j++)
            #pragma unroll
            for (int e = 0; e < 4; e++) acc[t][j][e] = 0.f;

    gemm_core(sb, Agh + (size_t)rowBase * Dm, Agl + (size_t)rowBase * Dm,
              Bg + (size_t)colBase * Dm, tid, lane, wr, wc, acc);

    const int er = lane >> 2, ec = (lane & 3) * 2;
    const int which = colBase >> 10;            // 0=Q 1=K 2=V
    const float scale = which == 0 ? 0.125f * 1.4426950408889634f : 1.0f;
    #pragma unroll
    for (int t = 0; t < 4; t++) {
        #pragma unroll
        for (int j = 0; j < 8; j++) {
            int m0 = rowBase + wr * 64 + t * 16 + er;
            int n  = (colBase & 1023) + wc * 64 + j * 8 + ec;
            int h = n >> 6, hd = n & 63;
            #pragma unroll
            for (int half = 0; half < 2; half++) {
                int m = m0 + half * 8;
                int b = m >> 11, s = m & 2047;
                size_t o = ((size_t)((b * Hh + h) * Sq + s)) * HDc + hd;
                float v0 = acc[t][j][2*half] * scale, v1 = acc[t][j][2*half+1] * scale;
                if (which == 0) {
                    uint32_t lo;
                    uint32_t hi = h2split(v0, v1, lo);
                    *(uint32_t*)&Qh[o] = hi;
                    *(uint32_t*)&Ql[o] = lo;
                } else {
                    __half* d = which == 1 ? Kf : Vf;
                    *(uint32_t*)&d[o] = h2pack(v0, v1);
                }
            }
        }
    }
}

// Output projection: C[4096][1024] fp32 = AH/AL @ WO^T
__global__ __launch_bounds__(128) void wo_gemm(
    const __half* __restrict__ Agh, const __half* __restrict__ Agl,
    const __half* __restrict__ Bg, float* __restrict__ dst)
{
    extern __shared__ char smc[];
    const uint32_t sb = smem_u32(smc);
    const int tid = threadIdx.x, lane = tid & 31, w = tid >> 5;
    const int wr = w >> 1, wc = w & 1;
    const int rowBase = blockIdx.y * 128, colBase = blockIdx.x * 128;

    float acc[4][8][4];
    #pragma unroll
    for (int t = 0; t < 4; t++)
        #pragma unroll
        for (int j = 0; j < 8; j++)
            #pragma unroll
            for (int e = 0; e < 4; e++) acc[t][j][e] = 0.f;

    gemm_core(sb, Agh + (size_t)rowBase * Dm, Agl + (size_t)rowBase * Dm,
              Bg + (size_t)colBase * Dm, tid, lane, wr, wc, acc);

    const int er = lane >> 2, ec = (lane & 3) * 2;
    #pragma unroll
    for (int t = 0; t < 4; t++) {
        #pragma unroll
        for (int j = 0; j < 8; j++) {
            int m0 = rowBase + wr * 64 + t * 16 + er;
            int n  = colBase + wc * 64 + j * 8 + ec;
            *(float2*)&dst[(size_t)m0 * Dm + n] = make_float2(acc[t][j][0], acc[t][j][1]);
            *(float2*)&dst[(size_t)(m0 + 8) * Dm + n] = make_float2(acc[t][j][2], acc[t][j][3]);
        }
    }
}

// ---------------------------------------------------------------------------
// HMMA flash attention: 256 thr, 8 warps x 16 q-rows, 64-key tiles,
// 2-stage cp.async. QK: 2 MMA (Q split), PV: 1 MMA.
// Softmax: ex2.approx.f16x2 (halved MUFU), l via ones-column MMA
// (exact fp16-consistent row sums, no end shuffles).
// ---------------------------------------------------------------------------
#define AP 72
#define KTB (64*AP*2)      // 9216
#define QTB (128*AP*2)     // 18432
#define QB  (2*QTB)        // 36864
#define STG (2*KTB)        // 18432 (K, V)
#define ASMEM (QB + 2*STG) // 73728

__global__ __launch_bounds__(256) void attn_mma(
    const __half* __restrict__ Qhg, const __half* __restrict__ Qlg,
    const __half* __restrict__ Kfg, const __half* __restrict__ Vfg,
    __half* __restrict__ AH, __half* __restrict__ AL)
{
    extern __shared__ char smc[];
    const uint32_t sb = smem_u32(smc);
    const uint32_t sQh = sb, sQl = sb + QTB;

    const int tid = threadIdx.x, lane = tid & 31, w = tid >> 5;
    const int q0 = ((int)gridDim.x - 1 - (int)blockIdx.x) * 128;  // longest-first
    const int h  = blockIdx.y;
    const int b  = blockIdx.z;

    const size_t hb = (size_t)((b * Hh + h) * Sq) * HDc;
    const __half* Qhb = Qhg + hb;
    const __half* Qlb = Qlg + hb;
    const __half* Kfb = Kfg + hb;
    const __half* Vfb = Vfg + hb;

    for (int i = tid; i < 1024; i += 256) {
        int r = i >> 3, c = (i & 7) * 8;
        uint32_t off = (uint32_t)(r * AP + c) * 2;
        *(uint4*)(smc + off)       = *(const uint4*)&Qhb[(size_t)(q0 + r) * HDc + c];
        *(uint4*)(smc + QTB + off) = *(const uint4*)&Qlb[(size_t)(q0 + r) * HDc + c];
    }

    const int nTiles = q0 / 64 + 2;

    auto issue = [&](int kt, int st) {
        const uint32_t base = sb + QB + st * STG;
        #pragma unroll
        for (int p = 0; p < 2; p++) {
            int i = tid + p * 256;
            int r = i >> 3, c = (i & 7) * 8;
            uint32_t so = (uint32_t)(r * AP + c) * 2;
            size_t go = (size_t)(kt * 64 + r) * HDc + c;
            cp16(base + so, Kfb + go);
            cp16(base + KTB + so, Vfb + go);
        }
        cp_commit();
    };

    float m0 = -INFINITY, m1 = -INFINITY;
    float o[8][4];
    float ol[4];   // ones-column accumulator: ol[0]/ol[1] row er, ol[2]/ol[3] row er+8
    #pragma unroll
    for (int j = 0; j < 8; j++)
        #pragma unroll
        for (int e = 0; e < 4; e++) o[j][e] = 0.f;
    ol[0] = ol[1] = ol[2] = ol[3] = 0.f;

    const int er = lane >> 2, ec = (lane & 3) * 2;
    const int wrow = q0 + w * 16;

    issue(0, 0);

    for (int kt = 0; kt < nTiles; kt++) {
        cp_wait0();
        __syncthreads();
        if (kt + 1 < nTiles) issue(kt + 1, (kt + 1) & 1);

        if (kt * 64 <= wrow + 15) {
            const uint32_t base = sb + QB + (kt & 1) * STG;
            const uint32_t sK = base, sV = base + KTB;

            float s[8][4];
            #pragma unroll
            for (int j = 0; j < 8; j++)
                #pragma unroll
                for (int e = 0; e < 4; e++) s[j][e] = 0.f;

            #pragma unroll
            for (int ks = 0; ks < 4; ks++) {
                uint32_t aoff = (uint32_t)(((w * 16 + (lane & 15)) * AP + ks * 16 + (lane >> 4) * 8) * 2);
                uint32_t qh[4], ql[4];
                ldsm_x4(qh, sQh + aoff);
                ldsm_x4(ql, sQl + aoff);
                #pragma unroll
                for (int j = 0; j < 8; j++) {
                    uint32_t boff = (uint32_t)(((j * 8 + (lane & 7)) * AP + ks * 16 + ((lane >> 3) & 1) * 8) * 2);
                    uint32_t kf[2];
                    ldsm_x2(kf, sK + boff);
                    mma16816(s[j], qh, kf);
                    mma16816(s[j], ql, kf);
                }
            }

            const int row0 = wrow + er, row1 = row0 + 8;
            if (kt * 64 + 63 > row0) {
                #pragma unroll
                for (int j = 0; j < 8; j++) {
                    int k = kt * 64 + j * 8 + ec;
                    if (k     > row0) s[j][0] = -INFINITY;
                    if (k + 1 > row0) s[j][1] = -INFINITY;
                    if (k     > row1) s[j][2] = -INFINITY;
                    if (k + 1 > row1) s[j][3] = -INFINITY;
                }
            }

            float rm0 = -INFINITY, rm1 = -INFINITY;
            #pragma unroll
            for (int j = 0; j < 8; j++) {
                rm0 = fmaxf(rm0, fmaxf(s[j][0], s[j][1]));
                rm1 = fmaxf(rm1, fmaxf(s[j][2], s[j][3]));
            }
            rm0 = fmaxf(rm0, __shfl_xor_sync(0xffffffffu, rm0, 1));
            rm0 = fmaxf(rm0, __shfl_xor_sync(0xffffffffu, rm0, 2));
            rm1 = fmaxf(rm1, __shfl_xor_sync(0xffffffffu, rm1, 1));
            rm1 = fmaxf(rm1, __shfl_xor_sync(0xffffffffu, rm1, 2));
            float mn0 = fmaxf(m0, rm0), mn1 = fmaxf(m1, rm1);
            float c0 = ex2f(m0 - mn0), c1 = ex2f(m1 - mn1);
            m0 = mn0; m1 = mn1;

            // P = 2^(s-m) directly in fp16 pairs (ex2.approx.f16x2)
            uint32_t ph0[8], ph1[8];
            #pragma unroll
            for (int j = 0; j < 8; j++) {
                ph0[j] = ex2h2(h2pack(s[j][0] - m0, s[j][1] - m0));
                ph1[j] = ex2h2(h2pack(s[j][2] - m1, s[j][3] - m1));
                o[j][0] *= c0; o[j][1] *= c0;
                o[j][2] *= c1; o[j][3] *= c1;
            }
            ol[0] *= c0; ol[1] *= c0;
            ol[2] *= c1; ol[3] *= c1;

            const uint32_t ones2[2] = {0x3C003C00u, 0x3C003C00u};
            #pragma unroll
            for (int aj = 0; aj < 4; aj++) {
                uint32_t pp[4];
                pp[0] = ph0[2*aj];
                pp[1] = ph1[2*aj];
                pp[2] = ph0[2*aj+1];
                pp[3] = ph1[2*aj+1];
                mma16816(ol, pp, ones2);   // row-sum of P (denominator)
                #pragma unroll
                for (int j = 0; j < 8; j++) {
                    uint32_t voff = (uint32_t)(((aj * 16 + (lane & 7) + ((lane >> 3) & 1) * 8) * AP + j * 8) * 2);
                    uint32_t vf[2];
                    ldsm_x2t(vf, sV + voff);
                    mma16816(o[j], pp, vf);
                }
            }
        }
    }

    float i0 = 1.f / ol[0], i1 = 1.f / ol[2];

    const int row0 = wrow + er;
    #pragma unroll
    for (int j = 0; j < 8; j++) {
        int dim = j * 8 + ec;
        size_t o0 = (size_t)(b * Sq + row0) * Dm + h * HDc + dim;
        size_t o1 = (size_t)(b * Sq + row0 + 8) * Dm + h * HDc + dim;
        uint32_t lo;
        uint32_t hi = h2split(o[j][0] * i0, o[j][1] * i0, lo);
        *(uint32_t*)&AH[o0] = hi; *(uint32_t*)&AL[o0] = lo;
        hi = h2split(o[j][2] * i1, o[j][3] * i1, lo);
        *(uint32_t*)&AH[o1] = hi; *(uint32_t*)&AL[o1] = lo;
    }
}

// ---------------------------------------------------------------------------
extern "C" void kernel_launch(void* const* d_in, const int* in_sizes, int n_in,
                              void* d_out, int out_size)
{
    (void)in_sizes; (void)n_in; (void)out_size;
    const float* x  = (const float*)d_in[0];
    const float* WQ = (const float*)d_in[1];
    const float* WK = (const float*)d_in[2];
    const float* WV = (const float*)d_in[3];
    const float* WO = (const float*)d_in[4];
    float* out = (float*)d_out;

    __half *xh, *xl, *wf, *ah, *al, *qh, *ql, *kf, *vf;
    cudaGetSymbolAddress((void**)&xh, g_Xh);
    cudaGetSymbolAddress((void**)&xl, g_Xl);
    cudaGetSymbolAddress((void**)&wf, g_Wf);
    cudaGetSymbolAddress((void**)&ah, g_AH);
    cudaGetSymbolAddress((void**)&al, g_AL);
    cudaGetSymbolAddress((void**)&qh, g_Qh);
    cudaGetSymbolAddress((void**)&ql, g_Ql);
    cudaGetSymbolAddress((void**)&kf, g_Kf);
    cudaGetSymbolAddress((void**)&vf, g_Vf);

    static int attrs_set = 0;
    int gsmem = 2 * STAGEB;        // 61440
    int asmem = ASMEM;             // 73728
    if (!attrs_set) {
        cudaFuncSetAttribute(qkv_gemm, cudaFuncAttributeMaxDynamicSharedMemorySize, gsmem);
        cudaFuncSetAttribute(wo_gemm,  cudaFuncAttributeMaxDynamicSharedMemorySize, gsmem);
        cudaFuncSetAttribute(attn_mma, cudaFuncAttributeMaxDynamicSharedMemorySize, asmem);
        attrs_set = 1;
    }

    convx_k<<<Mtot * Dm / 4 / 256, 256>>>(x, xh, xl);
    convw_k<<<dim3(32, 32, 4), dim3(32, 8)>>>(WQ, WK, WV, WO, wf);

    qkv_gemm<<<dim3(3 * Dm / 128, Mtot / 128), 128, gsmem>>>(
        xh, xl, wf, qh, ql, kf, vf);

    attn_mma<<<dim3(Sq / 128, Hh, Bq), 256, asmem>>>(qh, ql, kf, vf, ah, al);

    wo_gemm<<<dim3(Dm / 128, Mtot / 128), 128, gsmem>>>(
        ah, al, wf + 3 * (size_t)Dm * Dm, out);
}

// round 13
// speedup vs baseline: 1.2129x; 1.1709x over previous
#include <cuda_runtime.h>
#include <cuda_fp16.h>
#include <math.h>
#include <stdint.h>

// Problem constants
#define Bq  2
#define Sq  2048
#define Dm  1024
#define Hh  16
#define HDc 64
#define Mtot (Bq*Sq)   // 4096

// ---------------- device scratch (fp16) ----------------
__device__ __half g_Xh[Mtot*Dm], g_Xl[Mtot*Dm];   // x split hi/lo
__device__ __half g_Wf[4][Dm*Dm];                 // W^T single fp16, [N][K]
__device__ __half g_Qh[Mtot*Dm], g_Ql[Mtot*Dm];   // Q split, pre-scaled 0.125*log2e
__device__ __half g_Kf[Mtot*Dm], g_Vf[Mtot*Dm];   // K/V single
__device__ __half g_AH[Mtot*Dm];                  // attention out single fp16

// ---------------- helpers ----------------
__device__ __forceinline__ uint32_t smem_u32(const void* p) {
    uint32_t a;
    asm("{ .reg .u64 t; cvta.to.shared.u64 t, %1; cvt.u32.u64 %0, t; }" : "=r"(a) : "l"(p));
    return a;
}
__device__ __forceinline__ void cp16(uint32_t saddr, const void* gptr) {
    asm volatile("cp.async.cg.shared.global [%0], [%1], 16;" :: "r"(saddr), "l"(gptr) : "memory");
}
__device__ __forceinline__ void cp_commit() {
    asm volatile("cp.async.commit_group;" ::: "memory");
}
__device__ __forceinline__ void cp_wait0() {
    asm volatile("cp.async.wait_group 0;" ::: "memory");
}
__device__ __forceinline__ void ldsm_x4(uint32_t* r, uint32_t a) {
    asm volatile("ldmatrix.sync.aligned.m8n8.x4.shared.b16 {%0,%1,%2,%3}, [%4];"
                 : "=r"(r[0]), "=r"(r[1]), "=r"(r[2]), "=r"(r[3]) : "r"(a));
}
__device__ __forceinline__ void ldsm_x2(uint32_t* r, uint32_t a) {
    asm volatile("ldmatrix.sync.aligned.m8n8.x2.shared.b16 {%0,%1}, [%2];"
                 : "=r"(r[0]), "=r"(r[1]) : "r"(a));
}
__device__ __forceinline__ void ldsm_x2t(uint32_t* r, uint32_t a) {
    asm volatile("ldmatrix.sync.aligned.m8n8.x2.trans.shared.b16 {%0,%1}, [%2];"
                 : "=r"(r[0]), "=r"(r[1]) : "r"(a));
}
__device__ __forceinline__ void mma16816(float* c, const uint32_t* a, const uint32_t* b) {
    asm volatile(
        "mma.sync.aligned.m16n8k16.row.col.f32.f16.f16.f32 "
        "{%0,%1,%2,%3}, {%4,%5,%6,%7}, {%8,%9}, {%0,%1,%2,%3};"
        : "+f"(c[0]), "+f"(c[1]), "+f"(c[2]), "+f"(c[3])
        : "r"(a[0]), "r"(a[1]), "r"(a[2]), "r"(a[3]), "r"(b[0]), "r"(b[1]));
}
__device__ __forceinline__ float ex2f(float x) {
    float y;
    asm("ex2.approx.f32 %0, %1;" : "=f"(y) : "f"(x));
    return y;
}
__device__ __forceinline__ uint32_t ex2h2(uint32_t x) {
    uint32_t y;
    asm("ex2.approx.f16x2 %0, %1;" : "=r"(y) : "r"(x));
    return y;
}
__device__ __forceinline__ uint32_t h2pack(float a, float b) {
    __half2 h = __floats2half2_rn(a, b);
    return *(uint32_t*)&h;
}
__device__ __forceinline__ uint32_t h2split(float a, float b, uint32_t& lo) {
    __half ha = __float2half_rn(a), hb = __float2half_rn(b);
    __half la = __float2half_rn(a - __half2float(ha));
    __half lb = __float2half_rn(b - __half2float(hb));
    uint16_t uha = *(uint16_t*)&ha, uhb = *(uint16_t*)&hb;
    uint16_t ula = *(uint16_t*)&la, ulb = *(uint16_t*)&lb;
    lo = (uint32_t)ula | ((uint32_t)ulb << 16);
    return (uint32_t)uha | ((uint32_t)uhb << 16);
}

// ---------------------------------------------------------------------------
// conversion kernels
// ---------------------------------------------------------------------------
__global__ __launch_bounds__(256) void convx_k(const float* __restrict__ X,
                                               __half* __restrict__ H,
                                               __half* __restrict__ L)
{
    int i = blockIdx.x * blockDim.x + threadIdx.x;
    float4 v = ((const float4*)X)[i];
    uint32_t l0, l1;
    uint32_t h0 = h2split(v.x, v.y, l0);
    uint32_t h1 = h2split(v.z, v.w, l1);
    ((uint2*)H)[i] = make_uint2(h0, h1);
    ((uint2*)L)[i] = make_uint2(l0, l1);
}

__global__ __launch_bounds__(256) void convw_k(const float* __restrict__ W0,
                                               const float* __restrict__ W1,
                                               const float* __restrict__ W2,
                                               const float* __restrict__ W3,
                                               __half* __restrict__ T)
{
    __shared__ float t[32][33];
    const int z = blockIdx.z;
    const float* W = z == 0 ? W0 : (z == 1 ? W1 : (z == 2 ? W2 : W3));
    __half* th = T + (size_t)z * Dm * Dm;
    int n0 = blockIdx.x * 32, k0 = blockIdx.y * 32;
    int tx = threadIdx.x, ty = threadIdx.y;
    #pragma unroll
    for (int j = ty; j < 32; j += 8)
        t[j][tx] = W[(size_t)(k0 + j) * Dm + n0 + tx];
    __syncthreads();
    #pragma unroll
    for (int j = ty; j < 32; j += 8)
        th[(size_t)(n0 + j) * Dm + k0 + tx] = __float2half_rn(t[tx][j]);
}

// ---------------------------------------------------------------------------
// GEMM core: CTA 128x128, 4 warps (64x64), BK=32, 2-stage pipeline.
// NT=2: C = Ah@B + Al@B.  NT=1: C = Ah@B (skips Al loads + MMAs).
// ---------------------------------------------------------------------------
#define GP 40
#define MATB (128*GP*2)   // 10240
#define STAGEB (3*MATB)   // 30720

template<int NT>
__device__ __forceinline__ void gemm_core(
    const uint32_t sb,
    const __half* __restrict__ gAh, const __half* __restrict__ gAl,
    const __half* __restrict__ gB,
    int tid, int lane, int wr, int wc, float acc[4][8][4])
{
    auto issue = [&](int kt, int buf) {
        const int kc = kt * 32;
        const uint32_t base = sb + buf * STAGEB;
        #pragma unroll
        for (int p = 0; p < 4; p++) {
            int i = tid + p * 128;
            int r = i >> 2, c = i & 3;
            uint32_t so = (uint32_t)(r * (GP*2) + c * 16);
            size_t go = (size_t)r * Dm + kc + c * 8;
            cp16(base + 0*MATB + so, gAh + go);
            if (NT == 2) cp16(base + 1*MATB + so, gAl + go);
            cp16(base + 2*MATB + so, gB  + go);
        }
        cp_commit();
    };

    const int aRow = wr * 64 + (lane & 15);
    const int aKh  = (lane >> 4) * 8;
    const int bRow = wc * 64 + (lane & 7);
    const int bKh  = ((lane >> 3) & 1) * 8;

    issue(0, 0);

    for (int kt = 0; kt < 32; kt++) {
        cp_wait0();
        __syncthreads();
        if (kt + 1 < 32) issue(kt + 1, (kt + 1) & 1);

        const uint32_t base = sb + (kt & 1) * STAGEB;
        #pragma unroll
        for (int kk = 0; kk < 2; kk++) {
            uint32_t bf[8][2];
            #pragma unroll
            for (int j = 0; j < 8; j++) {
                uint32_t ba = base + 2*MATB +
                    (uint32_t)(((bRow + j * 8) * GP + kk * 16 + bKh) * 2);
                ldsm_x2(bf[j], ba);
            }
            #pragma unroll
            for (int t = 0; t < 4; t++) {
                uint32_t aa = base +
                    (uint32_t)(((aRow + t * 16) * GP + kk * 16 + aKh) * 2);
                uint32_t ah[4], al[4];
                ldsm_x4(ah, aa);
                if (NT == 2) ldsm_x4(al, aa + MATB);
                #pragma unroll
                for (int j = 0; j < 8; j++) {
                    mma16816(acc[t][j], ah, bf[j]);
                    if (NT == 2) mma16816(acc[t][j], al, bf[j]);
                }
            }
        }
    }
}

// Fused QKV projection: C[4096][3072] = X @ [WQ|WK|WV]^T
// Q columns: 2-term X split. K/V columns: single-term (calibrated precision).
__global__ __launch_bounds__(128) void qkv_gemm(
    const __half* __restrict__ Agh, const __half* __restrict__ Agl,
    const __half* __restrict__ Bg,
    __half* __restrict__ Qh, __half* __restrict__ Ql,
    __half* __restrict__ Kf, __half* __restrict__ Vf)
{
    extern __shared__ char smc[];
    const uint32_t sb = smem_u32(smc);
    const int tid = threadIdx.x, lane = tid & 31, w = tid >> 5;
    const int wr = w >> 1, wc = w & 1;
    const int rowBase = blockIdx.y * 128, colBase = blockIdx.x * 128;
    const int which = colBase >> 10;            // 0=Q 1=K 2=V

    float acc[4][8][4];
    #pragma unroll
    for (int t = 0; t < 4; t++)
        #pragma unroll
        for (int j = 0; j < 8; j++)
            #pragma unroll
            for (int e = 0; e < 4; e++) acc[t][j][e] = 0.f;

    if (which == 0)
        gemm_core<2>(sb, Agh + (size_t)rowBase * Dm, Agl + (size_t)rowBase * Dm,
                     Bg + (size_t)colBase * Dm, tid, lane, wr, wc, acc);
    else
        gemm_core<1>(sb, Agh + (size_t)rowBase * Dm, Agl + (size_t)rowBase * Dm,
                     Bg + (size_t)colBase * Dm, tid, lane, wr, wc, acc);

    const int er = lane >> 2, ec = (lane & 3) * 2;
    const float scale = which == 0 ? 0.125f * 1.4426950408889634f : 1.0f;
    #pragma unroll
    for (int t = 0; t < 4; t++) {
        #pragma unroll
        for (int j = 0; j < 8; j++) {
            int m0 = rowBase + wr * 64 + t * 16 + er;
            int n  = (colBase & 1023) + wc * 64 + j * 8 + ec;
            int h = n >> 6, hd = n & 63;
            #pragma unroll
            for (int half = 0; half < 2; half++) {
                int m = m0 + half * 8;
                int b = m >> 11, s = m & 2047;
                size_t o = ((size_t)((b * Hh + h) * Sq + s)) * HDc + hd;
                float v0 = acc[t][j][2*half] * scale, v1 = acc[t][j][2*half+1] * scale;
                if (which == 0) {
                    uint32_t lo;
                    uint32_t hi = h2split(v0, v1, lo);
                    *(uint32_t*)&Qh[o] = hi;
                    *(uint32_t*)&Ql[o] = lo;
                } else {
                    __half* d = which == 1 ? Kf : Vf;
                    *(uint32_t*)&d[o] = h2pack(v0, v1);
                }
            }
        }
    }
}

// Output projection: C[4096][1024] fp32 = AH @ WO^T (single-term A)
__global__ __launch_bounds__(128) void wo_gemm(
    const __half* __restrict__ Ag, const __half* __restrict__ Bg,
    float* __restrict__ dst)
{
    extern __shared__ char smc[];
    const uint32_t sb = smem_u32(smc);
    const int tid = threadIdx.x, lane = tid & 31, w = tid >> 5;
    const int wr = w >> 1, wc = w & 1;
    const int rowBase = blockIdx.y * 128, colBase = blockIdx.x * 128;

    float acc[4][8][4];
    #pragma unroll
    for (int t = 0; t < 4; t++)
        #pragma unroll
        for (int j = 0; j < 8; j++)
            #pragma unroll
            for (int e = 0; e < 4; e++) acc[t][j][e] = 0.f;

    gemm_core<1>(sb, Ag + (size_t)rowBase * Dm, Ag + (size_t)rowBase * Dm,
                 Bg + (size_t)colBase * Dm, tid, lane, wr, wc, acc);

    const int er = lane >> 2, ec = (lane & 3) * 2;
    #pragma unroll
    for (int t = 0; t < 4; t++) {
        #pragma unroll
        for (int j = 0; j < 8; j++) {
            int m0 = rowBase + wr * 64 + t * 16 + er;
            int n  = colBase + wc * 64 + j * 8 + ec;
            *(float2*)&dst[(size_t)m0 * Dm + n] = make_float2(acc[t][j][0], acc[t][j][1]);
            *(float2*)&dst[(size_t)(m0 + 8) * Dm + n] = make_float2(acc[t][j][2], acc[t][j][3]);
        }
    }
}

// ---------------------------------------------------------------------------
// HMMA flash attention (R12): 256 thr, 8 warps x 16 q-rows, 64-key tiles,
// 2-stage cp.async. QK: 2 MMA (Q split), PV: 1 MMA, l via ones-column MMA,
// ex2.approx.f16x2 softmax. Output: single fp16 AH.
// ---------------------------------------------------------------------------
#define AP 72
#define KTB (64*AP*2)      // 9216
#define QTB (128*AP*2)     // 18432
#define QB  (2*QTB)        // 36864
#define STG (2*KTB)        // 18432 (K, V)
#define ASMEM (QB + 2*STG) // 73728

__global__ __launch_bounds__(256) void attn_mma(
    const __half* __restrict__ Qhg, const __half* __restrict__ Qlg,
    const __half* __restrict__ Kfg, const __half* __restrict__ Vfg,
    __half* __restrict__ AH)
{
    extern __shared__ char smc[];
    const uint32_t sb = smem_u32(smc);
    const uint32_t sQh = sb, sQl = sb + QTB;

    const int tid = threadIdx.x, lane = tid & 31, w = tid >> 5;
    const int q0 = ((int)gridDim.x - 1 - (int)blockIdx.x) * 128;  // longest-first
    const int h  = blockIdx.y;
    const int b  = blockIdx.z;

    const size_t hb = (size_t)((b * Hh + h) * Sq) * HDc;
    const __half* Qhb = Qhg + hb;
    const __half* Qlb = Qlg + hb;
    const __half* Kfb = Kfg + hb;
    const __half* Vfb = Vfg + hb;

    for (int i = tid; i < 1024; i += 256) {
        int r = i >> 3, c = (i & 7) * 8;
        uint32_t off = (uint32_t)(r * AP + c) * 2;
        *(uint4*)(smc + off)       = *(const uint4*)&Qhb[(size_t)(q0 + r) * HDc + c];
        *(uint4*)(smc + QTB + off) = *(const uint4*)&Qlb[(size_t)(q0 + r) * HDc + c];
    }

    const int nTiles = q0 / 64 + 2;

    auto issue = [&](int kt, int st) {
        const uint32_t base = sb + QB + st * STG;
        #pragma unroll
        for (int p = 0; p < 2; p++) {
            int i = tid + p * 256;
            int r = i >> 3, c = (i & 7) * 8;
            uint32_t so = (uint32_t)(r * AP + c) * 2;
            size_t go = (size_t)(kt * 64 + r) * HDc + c;
            cp16(base + so, Kfb + go);
            cp16(base + KTB + so, Vfb + go);
        }
        cp_commit();
    };

    float m0 = -INFINITY, m1 = -INFINITY;
    float o[8][4];
    float ol[4];
    #pragma unroll
    for (int j = 0; j < 8; j++)
        #pragma unroll
        for (int e = 0; e < 4; e++) o[j][e] = 0.f;
    ol[0] = ol[1] = ol[2] = ol[3] = 0.f;

    const int er = lane >> 2, ec = (lane & 3) * 2;
    const int wrow = q0 + w * 16;

    issue(0, 0);

    for (int kt = 0; kt < nTiles; kt++) {
        cp_wait0();
        __syncthreads();
        if (kt + 1 < nTiles) issue(kt + 1, (kt + 1) & 1);

        if (kt * 64 <= wrow + 15) {
            const uint32_t base = sb + QB + (kt & 1) * STG;
            const uint32_t sK = base, sV = base + KTB;

            float s[8][4];
            #pragma unroll
            for (int j = 0; j < 8; j++)
                #pragma unroll
                for (int e = 0; e < 4; e++) s[j][e] = 0.f;

            #pragma unroll
            for (int ks = 0; ks < 4; ks++) {
                uint32_t aoff = (uint32_t)(((w * 16 + (lane & 15)) * AP + ks * 16 + (lane >> 4) * 8) * 2);
                uint32_t qh[4], ql[4];
                ldsm_x4(qh, sQh + aoff);
                ldsm_x4(ql, sQl + aoff);
                #pragma unroll
                for (int j = 0; j < 8; j++) {
                    uint32_t boff = (uint32_t)(((j * 8 + (lane & 7)) * AP + ks * 16 + ((lane >> 3) & 1) * 8) * 2);
                    uint32_t kf[2];
                    ldsm_x2(kf, sK + boff);
                    mma16816(s[j], qh, kf);
                    mma16816(s[j], ql, kf);
                }
            }

            const int row0 = wrow + er, row1 = row0 + 8;
            if (kt * 64 + 63 > row0) {
                #pragma unroll
                for (int j = 0; j < 8; j++) {
                    int k = kt * 64 + j * 8 + ec;
                    if (k     > row0) s[j][0] = -INFINITY;
                    if (k + 1 > row0) s[j][1] = -INFINITY;
                    if (k     > row1) s[j][2] = -INFINITY;
                    if (k + 1 > row1) s[j][3] = -INFINITY;
                }
            }

            float rm0 = -INFINITY, rm1 = -INFINITY;
            #pragma unroll
            for (int j = 0; j < 8; j++) {
                rm0 = fmaxf(rm0, fmaxf(s[j][0], s[j][1]));
                rm1 = fmaxf(rm1, fmaxf(s[j][2], s[j][3]));
            }
            rm0 = fmaxf(rm0, __shfl_xor_sync(0xffffffffu, rm0, 1));
            rm0 = fmaxf(rm0, __shfl_xor_sync(0xffffffffu, rm0, 2));
            rm1 = fmaxf(rm1, __shfl_xor_sync(0xffffffffu, rm1, 1));
            rm1 = fmaxf(rm1, __shfl_xor_sync(0xffffffffu, rm1, 2));
            float mn0 = fmaxf(m0, rm0), mn1 = fmaxf(m1, rm1);
            float c0 = ex2f(m0 - mn0), c1 = ex2f(m1 - mn1);
            m0 = mn0; m1 = mn1;

            uint32_t ph0[8], ph1[8];
            #pragma unroll
            for (int j = 0; j < 8; j++) {
                ph0[j] = ex2h2(h2pack(s[j][0] - m0, s[j][1] - m0));
                ph1[j] = ex2h2(h2pack(s[j][2] - m1, s[j][3] - m1));
                o[j][0] *= c0; o[j][1] *= c0;
                o[j][2] *= c1; o[j][3] *= c1;
            }
            ol[0] *= c0; ol[1] *= c0;
            ol[2] *= c1; ol[3] *= c1;

            const uint32_t ones2[2] = {0x3C003C00u, 0x3C003C00u};
            #pragma unroll
            for (int aj = 0; aj < 4; aj++) {
                uint32_t pp[4];
                pp[0] = ph0[2*aj];
                pp[1] = ph1[2*aj];
                pp[2] = ph0[2*aj+1];
                pp[3] = ph1[2*aj+1];
                mma16816(ol, pp, ones2);
                #pragma unroll
                for (int j = 0; j < 8; j++) {
                    uint32_t voff = (uint32_t)(((aj * 16 + (lane & 7) + ((lane >> 3) & 1) * 8) * AP + j * 8) * 2);
                    uint32_t vf[2];
                    ldsm_x2t(vf, sV + voff);
                    mma16816(o[j], pp, vf);
                }
            }
        }
    }

    float i0 = 1.f / ol[0], i1 = 1.f / ol[2];

    const int row0 = wrow + er;
    #pragma unroll
    for (int j = 0; j < 8; j++) {
        int dim = j * 8 + ec;
        size_t o0 = (size_t)(b * Sq + row0) * Dm + h * HDc + dim;
        size_t o1 = (size_t)(b * Sq + row0 + 8) * Dm + h * HDc + dim;
        *(uint32_t*)&AH[o0] = h2pack(o[j][0] * i0, o[j][1] * i0);
        *(uint32_t*)&AH[o1] = h2pack(o[j][2] * i1, o[j][3] * i1);
    }
}

// ---------------------------------------------------------------------------
extern "C" void kernel_launch(void* const* d_in, const int* in_sizes, int n_in,
                              void* d_out, int out_size)
{
    (void)in_sizes; (void)n_in; (void)out_size;
    const float* x  = (const float*)d_in[0];
    const float* WQ = (const float*)d_in[1];
    const float* WK = (const float*)d_in[2];
    const float* WV = (const float*)d_in[3];
    const float* WO = (const float*)d_in[4];
    float* out = (float*)d_out;

    __half *xh, *xl, *wf, *ah, *qh, *ql, *kf, *vf;
    cudaGetSymbolAddress((void**)&xh, g_Xh);
    cudaGetSymbolAddress((void**)&xl, g_Xl);
    cudaGetSymbolAddress((void**)&wf, g_Wf);
    cudaGetSymbolAddress((void**)&ah, g_AH);
    cudaGetSymbolAddress((void**)&qh, g_Qh);
    cudaGetSymbolAddress((void**)&ql, g_Ql);
    cudaGetSymbolAddress((void**)&kf, g_Kf);
    cudaGetSymbolAddress((void**)&vf, g_Vf);

    static int attrs_set = 0;
    int gsmem = 2 * STAGEB;        // 61440
    int asmem = ASMEM;             // 73728
    if (!attrs_set) {
        cudaFuncSetAttribute(qkv_gemm, cudaFuncAttributeMaxDynamicSharedMemorySize, gsmem);
        cudaFuncSetAttribute(wo_gemm,  cudaFuncAttributeMaxDynamicSharedMemorySize, gsmem);
        cudaFuncSetAttribute(attn_mma, cudaFuncAttributeMaxDynamicSharedMemorySize, asmem);
        attrs_set = 1;
    }

    convx_k<<<Mtot * Dm / 4 / 256, 256>>>(x, xh, xl);
    convw_k<<<dim3(32, 32, 4), dim3(32, 8)>>>(WQ, WK, WV, WO, wf);

    qkv_gemm<<<dim3(3 * Dm / 128, Mtot / 128), 128, gsmem>>>(
        xh, xl, wf, qh, ql, kf, vf);

    attn_mma<<<dim3(Sq / 128, Hh, Bq), 256, asmem>>>(qh, ql, kf, vf, ah);

    wo_gemm<<<dim3(Dm / 128, Mtot / 128), 128, gsmem>>>(
        ah, wf + 3 * (size_t)Dm * Dm, out);
}

// round 14
// speedup vs baseline: 1.5915x; 1.3121x over previous
#include <cuda_runtime.h>
#include <cuda_fp16.h>
#include <math.h>
#include <stdint.h>

// Problem constants
#define Bq  2
#define Sq  2048
#define Dm  1024
#define Hh  16
#define HDc 64
#define Mtot (Bq*Sq)   // 4096

// ---------------- device scratch (fp16) ----------------
__device__ __half g_Xf[Mtot*Dm];                  // x single fp16
__device__ __half g_Wf[4][Dm*Dm];                 // W^T single fp16, [N][K]
__device__ __half g_Qf[Mtot*Dm];                  // Q single, pre-scaled 0.125*log2e
__device__ __half g_Kf[Mtot*Dm], g_Vf[Mtot*Dm];   // K/V single
__device__ __half g_AH[Mtot*Dm];                  // attention out single fp16

// ---------------- helpers ----------------
__device__ __forceinline__ uint32_t smem_u32(const void* p) {
    uint32_t a;
    asm("{ .reg .u64 t; cvta.to.shared.u64 t, %1; cvt.u32.u64 %0, t; }" : "=r"(a) : "l"(p));
    return a;
}
__device__ __forceinline__ void cp16(uint32_t saddr, const void* gptr) {
    asm volatile("cp.async.cg.shared.global [%0], [%1], 16;" :: "r"(saddr), "l"(gptr) : "memory");
}
__device__ __forceinline__ void cp_commit() {
    asm volatile("cp.async.commit_group;" ::: "memory");
}
__device__ __forceinline__ void cp_wait0() {
    asm volatile("cp.async.wait_group 0;" ::: "memory");
}
__device__ __forceinline__ void ldsm_x4(uint32_t* r, uint32_t a) {
    asm volatile("ldmatrix.sync.aligned.m8n8.x4.shared.b16 {%0,%1,%2,%3}, [%4];"
                 : "=r"(r[0]), "=r"(r[1]), "=r"(r[2]), "=r"(r[3]) : "r"(a));
}
__device__ __forceinline__ void ldsm_x2(uint32_t* r, uint32_t a) {
    asm volatile("ldmatrix.sync.aligned.m8n8.x2.shared.b16 {%0,%1}, [%2];"
                 : "=r"(r[0]), "=r"(r[1]) : "r"(a));
}
__device__ __forceinline__ void ldsm_x2t(uint32_t* r, uint32_t a) {
    asm volatile("ldmatrix.sync.aligned.m8n8.x2.trans.shared.b16 {%0,%1}, [%2];"
                 : "=r"(r[0]), "=r"(r[1]) : "r"(a));
}
__device__ __forceinline__ void mma16816(float* c, const uint32_t* a, const uint32_t* b) {
    asm volatile(
        "mma.sync.aligned.m16n8k16.row.col.f32.f16.f16.f32 "
        "{%0,%1,%2,%3}, {%4,%5,%6,%7}, {%8,%9}, {%0,%1,%2,%3};"
        : "+f"(c[0]), "+f"(c[1]), "+f"(c[2]), "+f"(c[3])
        : "r"(a[0]), "r"(a[1]), "r"(a[2]), "r"(a[3]), "r"(b[0]), "r"(b[1]));
}
__device__ __forceinline__ float ex2f(float x) {
    float y;
    asm("ex2.approx.f32 %0, %1;" : "=f"(y) : "f"(x));
    return y;
}
__device__ __forceinline__ uint32_t ex2h2(uint32_t x) {
    uint32_t y;
    asm("ex2.approx.f16x2 %0, %1;" : "=r"(y) : "r"(x));
    return y;
}
__device__ __forceinline__ uint32_t h2pack(float a, float b) {
    __half2 h = __floats2half2_rn(a, b);
    return *(uint32_t*)&h;
}

// ---------------------------------------------------------------------------
// conversion kernels
// ---------------------------------------------------------------------------
__global__ __launch_bounds__(256) void convx_k(const float* __restrict__ X,
                                               __half* __restrict__ H)
{
    int i = blockIdx.x * blockDim.x + threadIdx.x;
    float4 v = ((const float4*)X)[i];
    ((uint2*)H)[i] = make_uint2(h2pack(v.x, v.y), h2pack(v.z, v.w));
}

__global__ __launch_bounds__(256) void convw_k(const float* __restrict__ W0,
                                               const float* __restrict__ W1,
                                               const float* __restrict__ W2,
                                               const float* __restrict__ W3,
                                               __half* __restrict__ T)
{
    __shared__ float t[32][33];
    const int z = blockIdx.z;
    const float* W = z == 0 ? W0 : (z == 1 ? W1 : (z == 2 ? W2 : W3));
    __half* th = T + (size_t)z * Dm * Dm;
    int n0 = blockIdx.x * 32, k0 = blockIdx.y * 32;
    int tx = threadIdx.x, ty = threadIdx.y;
    #pragma unroll
    for (int j = ty; j < 32; j += 8)
        t[j][tx] = W[(size_t)(k0 + j) * Dm + n0 + tx];
    __syncthreads();
    #pragma unroll
    for (int j = ty; j < 32; j += 8)
        th[(size_t)(n0 + j) * Dm + k0 + tx] = __float2half_rn(t[tx][j]);
}

// ---------------------------------------------------------------------------
// GEMM core: CTA 128x128, 4 warps (64x64), BK=32, 2-stage, single-term A.
// Stage = A tile + B tile = 2*MATB.
// ---------------------------------------------------------------------------
#define GP 40
#define MATB (128*GP*2)     // 10240
#define GSTG (2*MATB)       // 20480
#define GSMEM (2*GSTG)      // 40960

__device__ __forceinline__ void gemm_core1(
    const uint32_t sb,
    const __half* __restrict__ gA, const __half* __restrict__ gB,
    int tid, int lane, int wr, int wc, float acc[4][8][4])
{
    auto issue = [&](int kt, int buf) {
        const int kc = kt * 32;
        const uint32_t base = sb + buf * GSTG;
        #pragma unroll
        for (int p = 0; p < 4; p++) {
            int i = tid + p * 128;
            int r = i >> 2, c = i & 3;
            uint32_t so = (uint32_t)(r * (GP*2) + c * 16);
            size_t go = (size_t)r * Dm + kc + c * 8;
            cp16(base + so, gA + go);
            cp16(base + MATB + so, gB + go);
        }
        cp_commit();
    };

    const int aRow = wr * 64 + (lane & 15);
    const int aKh  = (lane >> 4) * 8;
    const int bRow = wc * 64 + (lane & 7);
    const int bKh  = ((lane >> 3) & 1) * 8;

    issue(0, 0);

    for (int kt = 0; kt < 32; kt++) {
        cp_wait0();
        __syncthreads();
        if (kt + 1 < 32) issue(kt + 1, (kt + 1) & 1);

        const uint32_t base = sb + (kt & 1) * GSTG;
        #pragma unroll
        for (int kk = 0; kk < 2; kk++) {
            uint32_t bf[8][2];
            #pragma unroll
            for (int j = 0; j < 8; j++) {
                uint32_t ba = base + MATB +
                    (uint32_t)(((bRow + j * 8) * GP + kk * 16 + bKh) * 2);
                ldsm_x2(bf[j], ba);
            }
            #pragma unroll
            for (int t = 0; t < 4; t++) {
                uint32_t aa = base +
                    (uint32_t)(((aRow + t * 16) * GP + kk * 16 + aKh) * 2);
                uint32_t af[4];
                ldsm_x4(af, aa);
                #pragma unroll
                for (int j = 0; j < 8; j++)
                    mma16816(acc[t][j], af, bf[j]);
            }
        }
    }
}

// Fused QKV projection: C[4096][3072] = X @ [WQ|WK|WV]^T, all single-term.
__global__ __launch_bounds__(128) void qkv_gemm(
    const __half* __restrict__ Xf, const __half* __restrict__ Bg,
    __half* __restrict__ Qf, __half* __restrict__ Kf, __half* __restrict__ Vf)
{
    extern __shared__ char smc[];
    const uint32_t sb = smem_u32(smc);
    const int tid = threadIdx.x, lane = tid & 31, w = tid >> 5;
    const int wr = w >> 1, wc = w & 1;
    const int rowBase = blockIdx.y * 128, colBase = blockIdx.x * 128;
    const int which = colBase >> 10;            // 0=Q 1=K 2=V

    float acc[4][8][4];
    #pragma unroll
    for (int t = 0; t < 4; t++)
        #pragma unroll
        for (int j = 0; j < 8; j++)
            #pragma unroll
            for (int e = 0; e < 4; e++) acc[t][j][e] = 0.f;

    gemm_core1(sb, Xf + (size_t)rowBase * Dm, Bg + (size_t)colBase * Dm,
               tid, lane, wr, wc, acc);

    const int er = lane >> 2, ec = (lane & 3) * 2;
    __half* dst = which == 0 ? Qf : (which == 1 ? Kf : Vf);
    const float scale = which == 0 ? 0.125f * 1.4426950408889634f : 1.0f;
    #pragma unroll
    for (int t = 0; t < 4; t++) {
        #pragma unroll
        for (int j = 0; j < 8; j++) {
            int m0 = rowBase + wr * 64 + t * 16 + er;
            int n  = (colBase & 1023) + wc * 64 + j * 8 + ec;
            int h = n >> 6, hd = n & 63;
            #pragma unroll
            for (int half = 0; half < 2; half++) {
                int m = m0 + half * 8;
                int b = m >> 11, s = m & 2047;
                size_t o = ((size_t)((b * Hh + h) * Sq + s)) * HDc + hd;
                *(uint32_t*)&dst[o] = h2pack(acc[t][j][2*half] * scale,
                                             acc[t][j][2*half+1] * scale);
            }
        }
    }
}

// Output projection: C[4096][1024] fp32 = AH @ WO^T
__global__ __launch_bounds__(128) void wo_gemm(
    const __half* __restrict__ Ag, const __half* __restrict__ Bg,
    float* __restrict__ dst)
{
    extern __shared__ char smc[];
    const uint32_t sb = smem_u32(smc);
    const int tid = threadIdx.x, lane = tid & 31, w = tid >> 5;
    const int wr = w >> 1, wc = w & 1;
    const int rowBase = blockIdx.y * 128, colBase = blockIdx.x * 128;

    float acc[4][8][4];
    #pragma unroll
    for (int t = 0; t < 4; t++)
        #pragma unroll
        for (int j = 0; j < 8; j++)
            #pragma unroll
            for (int e = 0; e < 4; e++) acc[t][j][e] = 0.f;

    gemm_core1(sb, Ag + (size_t)rowBase * Dm, Bg + (size_t)colBase * Dm,
               tid, lane, wr, wc, acc);

    const int er = lane >> 2, ec = (lane & 3) * 2;
    #pragma unroll
    for (int t = 0; t < 4; t++) {
        #pragma unroll
        for (int j = 0; j < 8; j++) {
            int m0 = rowBase + wr * 64 + t * 16 + er;
            int n  = colBase + wc * 64 + j * 8 + ec;
            *(float2*)&dst[(size_t)m0 * Dm + n] = make_float2(acc[t][j][0], acc[t][j][1]);
            *(float2*)&dst[(size_t)(m0 + 8) * Dm + n] = make_float2(acc[t][j][2], acc[t][j][3]);
        }
    }
}

// ---------------------------------------------------------------------------
// HMMA flash attention: 256 thr, 8 warps x 16 q-rows, 64-key tiles,
// 2-stage cp.async. All operands single fp16: QK 1 MMA, PV 1 MMA,
// l via ones-column MMA, ex2.approx.f16x2 softmax.
// ---------------------------------------------------------------------------
#define AP 72
#define KTB (64*AP*2)       // 9216
#define QTB (128*AP*2)      // 18432
#define STG (2*KTB)         // 18432 (K, V)
#define ASMEM (QTB + 2*STG) // 55296

__global__ __launch_bounds__(256) void attn_mma(
    const __half* __restrict__ Qfg, const __half* __restrict__ Kfg,
    const __half* __restrict__ Vfg, __half* __restrict__ AH)
{
    extern __shared__ char smc[];
    const uint32_t sb = smem_u32(smc);
    const uint32_t sQ = sb;

    const int tid = threadIdx.x, lane = tid & 31, w = tid >> 5;
    const int q0 = ((int)gridDim.x - 1 - (int)blockIdx.x) * 128;  // longest-first
    const int h  = blockIdx.y;
    const int b  = blockIdx.z;

    const size_t hb = (size_t)((b * Hh + h) * Sq) * HDc;
    const __half* Qfb = Qfg + hb;
    const __half* Kfb = Kfg + hb;
    const __half* Vfb = Vfg + hb;

    for (int i = tid; i < 1024; i += 256) {
        int r = i >> 3, c = (i & 7) * 8;
        uint32_t off = (uint32_t)(r * AP + c) * 2;
        *(uint4*)(smc + off) = *(const uint4*)&Qfb[(size_t)(q0 + r) * HDc + c];
    }

    const int nTiles = q0 / 64 + 2;

    auto issue = [&](int kt, int st) {
        const uint32_t base = sb + QTB + st * STG;
        #pragma unroll
        for (int p = 0; p < 2; p++) {
            int i = tid + p * 256;
            int r = i >> 3, c = (i & 7) * 8;
            uint32_t so = (uint32_t)(r * AP + c) * 2;
            size_t go = (size_t)(kt * 64 + r) * HDc + c;
            cp16(base + so, Kfb + go);
            cp16(base + KTB + so, Vfb + go);
        }
        cp_commit();
    };

    float m0 = -INFINITY, m1 = -INFINITY;
    float o[8][4];
    float ol[4];
    #pragma unroll
    for (int j = 0; j < 8; j++)
        #pragma unroll
        for (int e = 0; e < 4; e++) o[j][e] = 0.f;
    ol[0] = ol[1] = ol[2] = ol[3] = 0.f;

    const int er = lane >> 2, ec = (lane & 3) * 2;
    const int wrow = q0 + w * 16;

    issue(0, 0);

    for (int kt = 0; kt < nTiles; kt++) {
        cp_wait0();
        __syncthreads();
        if (kt + 1 < nTiles) issue(kt + 1, (kt + 1) & 1);

        if (kt * 64 <= wrow + 15) {
            const uint32_t base = sb + QTB + (kt & 1) * STG;
            const uint32_t sK = base, sV = base + KTB;

            float s[8][4];
            #pragma unroll
            for (int j = 0; j < 8; j++)
                #pragma unroll
                for (int e = 0; e < 4; e++) s[j][e] = 0.f;

            #pragma unroll
            for (int ks = 0; ks < 4; ks++) {
                uint32_t aoff = (uint32_t)(((w * 16 + (lane & 15)) * AP + ks * 16 + (lane >> 4) * 8) * 2);
                uint32_t qf[4];
                ldsm_x4(qf, sQ + aoff);
                #pragma unroll
                for (int j = 0; j < 8; j++) {
                    uint32_t boff = (uint32_t)(((j * 8 + (lane & 7)) * AP + ks * 16 + ((lane >> 3) & 1) * 8) * 2);
                    uint32_t kf[2];
                    ldsm_x2(kf, sK + boff);
                    mma16816(s[j], qf, kf);
                }
            }

            const int row0 = wrow + er, row1 = row0 + 8;
            if (kt * 64 + 63 > row0) {
                #pragma unroll
                for (int j = 0; j < 8; j++) {
                    int k = kt * 64 + j * 8 + ec;
                    if (k     > row0) s[j][0] = -INFINITY;
                    if (k + 1 > row0) s[j][1] = -INFINITY;
                    if (k     > row1) s[j][2] = -INFINITY;
                    if (k + 1 > row1) s[j][3] = -INFINITY;
                }
            }

            float rm0 = -INFINITY, rm1 = -INFINITY;
            #pragma unroll
            for (int j = 0; j < 8; j++) {
                rm0 = fmaxf(rm0, fmaxf(s[j][0], s[j][1]));
                rm1 = fmaxf(rm1, fmaxf(s[j][2], s[j][3]));
            }
            rm0 = fmaxf(rm0, __shfl_xor_sync(0xffffffffu, rm0, 1));
            rm0 = fmaxf(rm0, __shfl_xor_sync(0xffffffffu, rm0, 2));
            rm1 = fmaxf(rm1, __shfl_xor_sync(0xffffffffu, rm1, 1));
            rm1 = fmaxf(rm1, __shfl_xor_sync(0xffffffffu, rm1, 2));
            float mn0 = fmaxf(m0, rm0), mn1 = fmaxf(m1, rm1);
            float c0 = ex2f(m0 - mn0), c1 = ex2f(m1 - mn1);
            m0 = mn0; m1 = mn1;

            uint32_t ph0[8], ph1[8];
            #pragma unroll
            for (int j = 0; j < 8; j++) {
                ph0[j] = ex2h2(h2pack(s[j][0] - m0, s[j][1] - m0));
                ph1[j] = ex2h2(h2pack(s[j][2] - m1, s[j][3] - m1));
                o[j][0] *= c0; o[j][1] *= c0;
                o[j][2] *= c1; o[j][3] *= c1;
            }
            ol[0] *= c0; ol[1] *= c0;
            ol[2] *= c1; ol[3] *= c1;

            const uint32_t ones2[2] = {0x3C003C00u, 0x3C003C00u};
            #pragma unroll
            for (int aj = 0; aj < 4; aj++) {
                uint32_t pp[4];
                pp[0] = ph0[2*aj];
                pp[1] = ph1[2*aj];
                pp[2] = ph0[2*aj+1];
                pp[3] = ph1[2*aj+1];
                mma16816(ol, pp, ones2);
                #pragma unroll
                for (int j = 0; j < 8; j++) {
                    uint32_t voff = (uint32_t)(((aj * 16 + (lane & 7) + ((lane >> 3) & 1) * 8) * AP + j * 8) * 2);
                    uint32_t vf[2];
                    ldsm_x2t(vf, sV + voff);
                    mma16816(o[j], pp, vf);
                }
            }
        }
    }

    float i0 = 1.f / ol[0], i1 = 1.f / ol[2];

    const int row0 = wrow + er;
    #pragma unroll
    for (int j = 0; j < 8; j++) {
        int dim = j * 8 + ec;
        size_t o0 = (size_t)(b * Sq + row0) * Dm + h * HDc + dim;
        size_t o1 = (size_t)(b * Sq + row0 + 8) * Dm + h * HDc + dim;
        *(uint32_t*)&AH[o0] = h2pack(o[j][0] * i0, o[j][1] * i0);
        *(uint32_t*)&AH[o1] = h2pack(o[j][2] * i1, o[j][3] * i1);
    }
}

// ---------------------------------------------------------------------------
extern "C" void kernel_launch(void* const* d_in, const int* in_sizes, int n_in,
                              void* d_out, int out_size)
{
    (void)in_sizes; (void)n_in; (void)out_size;
    const float* x  = (const float*)d_in[0];
    const float* WQ = (const float*)d_in[1];
    const float* WK = (const float*)d_in[2];
    const float* WV = (const float*)d_in[3];
    const float* WO = (const float*)d_in[4];
    float* out = (float*)d_out;

    __half *xf, *wf, *ah, *qf, *kf, *vf;
    cudaGetSymbolAddress((void**)&xf, g_Xf);
    cudaGetSymbolAddress((void**)&wf, g_Wf);
    cudaGetSymbolAddress((void**)&ah, g_AH);
    cudaGetSymbolAddress((void**)&qf, g_Qf);
    cudaGetSymbolAddress((void**)&kf, g_Kf);
    cudaGetSymbolAddress((void**)&vf, g_Vf);

    static int attrs_set = 0;
    if (!attrs_set) {
        cudaFuncSetAttribute(qkv_gemm, cudaFuncAttributeMaxDynamicSharedMemorySize, GSMEM);
        cudaFuncSetAttribute(wo_gemm,  cudaFuncAttributeMaxDynamicSharedMemorySize, GSMEM);
        cudaFuncSetAttribute(attn_mma, cudaFuncAttributeMaxDynamicSharedMemorySize, ASMEM);
        attrs_set = 1;
    }

    convx_k<<<Mtot * Dm / 4 / 256, 256>>>(x, xf);
    convw_k<<<dim3(32, 32, 4), dim3(32, 8)>>>(WQ, WK, WV, WO, wf);

    qkv_gemm<<<dim3(3 * Dm / 128, Mtot / 128), 128, GSMEM>>>(
        xf, wf, qf, kf, vf);

    attn_mma<<<dim3(Sq / 128, Hh, Bq), 256, ASMEM>>>(qf, kf, vf, ah);

    wo_gemm<<<dim3(Dm / 128, Mtot / 128), 128, GSMEM>>>(
        ah, wf + 3 * (size_t)Dm * Dm, out);
}

// round 15
// speedup vs baseline: 1.6430x; 1.0324x over previous
#include <cuda_runtime.h>
#include <cuda_fp16.h>
#include <math.h>
#include <stdint.h>

// Problem constants
#define Bq  2
#define Sq  2048
#define Dm  1024
#define Hh  16
#define HDc 64
#define Mtot (Bq*Sq)   // 4096

// ---------------- device scratch (fp16) ----------------
__device__ __half g_Xf[Mtot*Dm];                  // x single fp16
__device__ __half g_Wf[4][Dm*Dm];                 // W^T single fp16, [N][K]
__device__ __half g_Qf[Mtot*Dm];                  // Q single, pre-scaled 0.125*log2e
__device__ __half g_Kf[Mtot*Dm], g_Vf[Mtot*Dm];   // K/V single
__device__ __half g_AH[Mtot*Dm];                  // attention out single fp16

// ---------------- helpers ----------------
__device__ __forceinline__ uint32_t smem_u32(const void* p) {
    uint32_t a;
    asm("{ .reg .u64 t; cvta.to.shared.u64 t, %1; cvt.u32.u64 %0, t; }" : "=r"(a) : "l"(p));
    return a;
}
__device__ __forceinline__ void cp16(uint32_t saddr, const void* gptr) {
    asm volatile("cp.async.cg.shared.global [%0], [%1], 16;" :: "r"(saddr), "l"(gptr) : "memory");
}
__device__ __forceinline__ void cp_commit() {
    asm volatile("cp.async.commit_group;" ::: "memory");
}
__device__ __forceinline__ void cp_wait0() {
    asm volatile("cp.async.wait_group 0;" ::: "memory");
}
__device__ __forceinline__ void ldsm_x4(uint32_t* r, uint32_t a) {
    asm volatile("ldmatrix.sync.aligned.m8n8.x4.shared.b16 {%0,%1,%2,%3}, [%4];"
                 : "=r"(r[0]), "=r"(r[1]), "=r"(r[2]), "=r"(r[3]) : "r"(a));
}
__device__ __forceinline__ void ldsm_x2(uint32_t* r, uint32_t a) {
    asm volatile("ldmatrix.sync.aligned.m8n8.x2.shared.b16 {%0,%1}, [%2];"
                 : "=r"(r[0]), "=r"(r[1]) : "r"(a));
}
__device__ __forceinline__ void ldsm_x2t(uint32_t* r, uint32_t a) {
    asm volatile("ldmatrix.sync.aligned.m8n8.x2.trans.shared.b16 {%0,%1}, [%2];"
                 : "=r"(r[0]), "=r"(r[1]) : "r"(a));
}
__device__ __forceinline__ void mma16816(float* c, const uint32_t* a, const uint32_t* b) {
    asm volatile(
        "mma.sync.aligned.m16n8k16.row.col.f32.f16.f16.f32 "
        "{%0,%1,%2,%3}, {%4,%5,%6,%7}, {%8,%9}, {%0,%1,%2,%3};"
        : "+f"(c[0]), "+f"(c[1]), "+f"(c[2]), "+f"(c[3])
        : "r"(a[0]), "r"(a[1]), "r"(a[2]), "r"(a[3]), "r"(b[0]), "r"(b[1]));
}
__device__ __forceinline__ uint32_t ex2h2(uint32_t x) {
    uint32_t y;
    asm("ex2.approx.f16x2 %0, %1;" : "=r"(y) : "r"(x));
    return y;
}
__device__ __forceinline__ uint32_t hmax2(uint32_t a, uint32_t b) {
    uint32_t y;
    asm("max.f16x2 %0, %1, %2;" : "=r"(y) : "r"(a), "r"(b));
    return y;
}
__device__ __forceinline__ uint32_t h2pack(float a, float b) {
    __half2 h = __floats2half2_rn(a, b);
    return *(uint32_t*)&h;
}

// ---------------------------------------------------------------------------
// conversion kernels
// ---------------------------------------------------------------------------
__global__ __launch_bounds__(256) void convx_k(const float* __restrict__ X,
                                               __half* __restrict__ H)
{
    int i = blockIdx.x * blockDim.x + threadIdx.x;
    float4 v = ((const float4*)X)[i];
    ((uint2*)H)[i] = make_uint2(h2pack(v.x, v.y), h2pack(v.z, v.w));
}

__global__ __launch_bounds__(256) void convw_k(const float* __restrict__ W0,
                                               const float* __restrict__ W1,
                                               const float* __restrict__ W2,
                                               const float* __restrict__ W3,
                                               __half* __restrict__ T)
{
    __shared__ float t[32][33];
    const int z = blockIdx.z;
    const float* W = z == 0 ? W0 : (z == 1 ? W1 : (z == 2 ? W2 : W3));
    __half* th = T + (size_t)z * Dm * Dm;
    int n0 = blockIdx.x * 32, k0 = blockIdx.y * 32;
    int tx = threadIdx.x, ty = threadIdx.y;
    #pragma unroll
    for (int j = ty; j < 32; j += 8)
        t[j][tx] = W[(size_t)(k0 + j) * Dm + n0 + tx];
    __syncthreads();
    #pragma unroll
    for (int j = ty; j < 32; j += 8)
        th[(size_t)(n0 + j) * Dm + k0 + tx] = __float2half_rn(t[tx][j]);
}

// ---------------------------------------------------------------------------
// GEMM core: CTA 128x128, 4 warps (64x64), BK=32, 2-stage, single-term A.
// ---------------------------------------------------------------------------
#define GP 40
#define MATB (128*GP*2)     // 10240
#define GSTG (2*MATB)       // 20480
#define GSMEM (2*GSTG)      // 40960

__device__ __forceinline__ void gemm_core1(
    const uint32_t sb,
    const __half* __restrict__ gA, const __half* __restrict__ gB,
    int tid, int lane, int wr, int wc, float acc[4][8][4])
{
    auto issue = [&](int kt, int buf) {
        const int kc = kt * 32;
        const uint32_t base = sb + buf * GSTG;
        #pragma unroll
        for (int p = 0; p < 4; p++) {
            int i = tid + p * 128;
            int r = i >> 2, c = i & 3;
            uint32_t so = (uint32_t)(r * (GP*2) + c * 16);
            size_t go = (size_t)r * Dm + kc + c * 8;
            cp16(base + so, gA + go);
            cp16(base + MATB + so, gB + go);
        }
        cp_commit();
    };

    const int aRow = wr * 64 + (lane & 15);
    const int aKh  = (lane >> 4) * 8;
    const int bRow = wc * 64 + (lane & 7);
    const int bKh  = ((lane >> 3) & 1) * 8;

    issue(0, 0);

    for (int kt = 0; kt < 32; kt++) {
        cp_wait0();
        __syncthreads();
        if (kt + 1 < 32) issue(kt + 1, (kt + 1) & 1);

        const uint32_t base = sb + (kt & 1) * GSTG;
        #pragma unroll
        for (int kk = 0; kk < 2; kk++) {
            uint32_t bf[8][2];
            #pragma unroll
            for (int j = 0; j < 8; j++) {
                uint32_t ba = base + MATB +
                    (uint32_t)(((bRow + j * 8) * GP + kk * 16 + bKh) * 2);
                ldsm_x2(bf[j], ba);
            }
            #pragma unroll
            for (int t = 0; t < 4; t++) {
                uint32_t aa = base +
                    (uint32_t)(((aRow + t * 16) * GP + kk * 16 + aKh) * 2);
                uint32_t af[4];
                ldsm_x4(af, aa);
                #pragma unroll
                for (int j = 0; j < 8; j++)
                    mma16816(acc[t][j], af, bf[j]);
            }
        }
    }
}

// Fused QKV projection: C[4096][3072] = X @ [WQ|WK|WV]^T, all single-term.
__global__ __launch_bounds__(128) void qkv_gemm(
    const __half* __restrict__ Xf, const __half* __restrict__ Bg,
    __half* __restrict__ Qf, __half* __restrict__ Kf, __half* __restrict__ Vf)
{
    extern __shared__ char smc[];
    const uint32_t sb = smem_u32(smc);
    const int tid = threadIdx.x, lane = tid & 31, w = tid >> 5;
    const int wr = w >> 1, wc = w & 1;
    const int rowBase = blockIdx.y * 128, colBase = blockIdx.x * 128;
    const int which = colBase >> 10;            // 0=Q 1=K 2=V

    float acc[4][8][4];
    #pragma unroll
    for (int t = 0; t < 4; t++)
        #pragma unroll
        for (int j = 0; j < 8; j++)
            #pragma unroll
            for (int e = 0; e < 4; e++) acc[t][j][e] = 0.f;

    gemm_core1(sb, Xf + (size_t)rowBase * Dm, Bg + (size_t)colBase * Dm,
               tid, lane, wr, wc, acc);

    const int er = lane >> 2, ec = (lane & 3) * 2;
    __half* dst = which == 0 ? Qf : (which == 1 ? Kf : Vf);
    const float scale = which == 0 ? 0.125f * 1.4426950408889634f : 1.0f;
    #pragma unroll
    for (int t = 0; t < 4; t++) {
        #pragma unroll
        for (int j = 0; j < 8; j++) {
            int m0 = rowBase + wr * 64 + t * 16 + er;
            int n  = (colBase & 1023) + wc * 64 + j * 8 + ec;
            int h = n >> 6, hd = n & 63;
            #pragma unroll
            for (int half = 0; half < 2; half++) {
                int m = m0 + half * 8;
                int b = m >> 11, s = m & 2047;
                size_t o = ((size_t)((b * Hh + h) * Sq + s)) * HDc + hd;
                *(uint32_t*)&dst[o] = h2pack(acc[t][j][2*half] * scale,
                                             acc[t][j][2*half+1] * scale);
            }
        }
    }
}

// Output projection: C[4096][1024] fp32 = AH @ WO^T
__global__ __launch_bounds__(128) void wo_gemm(
    const __half* __restrict__ Ag, const __half* __restrict__ Bg,
    float* __restrict__ dst)
{
    extern __shared__ char smc[];
    const uint32_t sb = smem_u32(smc);
    const int tid = threadIdx.x, lane = tid & 31, w = tid >> 5;
    const int wr = w >> 1, wc = w & 1;
    const int rowBase = blockIdx.y * 128, colBase = blockIdx.x * 128;

    float acc[4][8][4];
    #pragma unroll
    for (int t = 0; t < 4; t++)
        #pragma unroll
        for (int j = 0; j < 8; j++)
            #pragma unroll
            for (int e = 0; e < 4; e++) acc[t][j][e] = 0.f;

    gemm_core1(sb, Ag + (size_t)rowBase * Dm, Bg + (size_t)colBase * Dm,
               tid, lane, wr, wc, acc);

    const int er = lane >> 2, ec = (lane & 3) * 2;
    #pragma unroll
    for (int t = 0; t < 4; t++) {
        #pragma unroll
        for (int j = 0; j < 8; j++) {
            int m0 = rowBase + wr * 64 + t * 16 + er;
            int n  = colBase + wc * 64 + j * 8 + ec;
            *(float2*)&dst[(size_t)m0 * Dm + n] = make_float2(acc[t][j][0], acc[t][j][1]);
            *(float2*)&dst[(size_t)(m0 + 8) * Dm + n] = make_float2(acc[t][j][2], acc[t][j][3]);
        }
    }
}

// ---------------------------------------------------------------------------
// HMMA flash attention: 256 thr, 8 warps x 16 q-rows, 64-key tiles,
// 2-stage cp.async. Single fp16 everywhere: QK 1 MMA, PV 1 MMA,
// l via ones-column MMA. Q fragments hoisted to registers (16 regs).
// Packed-fp16 max shuffles; correction factors via one ex2.f16x2.
// ---------------------------------------------------------------------------
#define AP 72
#define KTB (64*AP*2)       // 9216
#define QTB (128*AP*2)      // 18432
#define STG (2*KTB)         // 18432 (K, V)
#define ASMEM (QTB + 2*STG) // 55296

__global__ __launch_bounds__(256, 2) void attn_mma(
    const __half* __restrict__ Qfg, const __half* __restrict__ Kfg,
    const __half* __restrict__ Vfg, __half* __restrict__ AH)
{
    extern __shared__ char smc[];
    const uint32_t sb = smem_u32(smc);
    const uint32_t sQ = sb;

    const int tid = threadIdx.x, lane = tid & 31, w = tid >> 5;
    const int q0 = ((int)gridDim.x - 1 - (int)blockIdx.x) * 128;  // longest-first
    const int h  = blockIdx.y;
    const int b  = blockIdx.z;

    const size_t hb = (size_t)((b * Hh + h) * Sq) * HDc;
    const __half* Qfb = Qfg + hb;
    const __half* Kfb = Kfg + hb;
    const __half* Vfb = Vfg + hb;

    for (int i = tid; i < 1024; i += 256) {
        int r = i >> 3, c = (i & 7) * 8;
        uint32_t off = (uint32_t)(r * AP + c) * 2;
        *(uint4*)(smc + off) = *(const uint4*)&Qfb[(size_t)(q0 + r) * HDc + c];
    }

    const int nTiles = q0 / 64 + 2;

    auto issue = [&](int kt, int st) {
        const uint32_t base = sb + QTB + st * STG;
        #pragma unroll
        for (int p = 0; p < 2; p++) {
            int i = tid + p * 256;
            int r = i >> 3, c = (i & 7) * 8;
            uint32_t so = (uint32_t)(r * AP + c) * 2;
            size_t go = (size_t)(kt * 64 + r) * HDc + c;
            cp16(base + so, Kfb + go);
            cp16(base + KTB + so, Vfb + go);
        }
        cp_commit();
    };

    issue(0, 0);
    __syncthreads();   // Q smem visible

    // hoist Q fragments (single fp16: 16 regs)
    uint32_t qf[4][4];
    #pragma unroll
    for (int ks = 0; ks < 4; ks++) {
        uint32_t aoff = (uint32_t)(((w * 16 + (lane & 15)) * AP + ks * 16 + (lane >> 4) * 8) * 2);
        ldsm_x4(qf[ks], sQ + aoff);
    }

    float m0 = -INFINITY, m1 = -INFINITY;
    float o[8][4];
    float ol[4];
    #pragma unroll
    for (int j = 0; j < 8; j++)
        #pragma unroll
        for (int e = 0; e < 4; e++) o[j][e] = 0.f;
    ol[0] = ol[1] = ol[2] = ol[3] = 0.f;

    const int er = lane >> 2, ec = (lane & 3) * 2;
    const int wrow = q0 + w * 16;

    for (int kt = 0; kt < nTiles; kt++) {
        cp_wait0();
        __syncthreads();
        if (kt + 1 < nTiles) issue(kt + 1, (kt + 1) & 1);

        if (kt * 64 <= wrow + 15) {
            const uint32_t base = sb + QTB + (kt & 1) * STG;
            const uint32_t sK = base, sV = base + KTB;

            float s[8][4];
            #pragma unroll
            for (int j = 0; j < 8; j++)
                #pragma unroll
                for (int e = 0; e < 4; e++) s[j][e] = 0.f;

            #pragma unroll
            for (int ks = 0; ks < 4; ks++) {
                #pragma unroll
                for (int j = 0; j < 8; j++) {
                    uint32_t boff = (uint32_t)(((j * 8 + (lane & 7)) * AP + ks * 16 + ((lane >> 3) & 1) * 8) * 2);
                    uint32_t kf[2];
                    ldsm_x2(kf, sK + boff);
                    mma16816(s[j], qf[ks], kf);
                }
            }

            const int row0 = wrow + er, row1 = row0 + 8;
            if (kt * 64 + 63 > row0) {
                #pragma unroll
                for (int j = 0; j < 8; j++) {
                    int k = kt * 64 + j * 8 + ec;
                    if (k     > row0) s[j][0] = -INFINITY;
                    if (k + 1 > row0) s[j][1] = -INFINITY;
                    if (k     > row1) s[j][2] = -INFINITY;
                    if (k + 1 > row1) s[j][3] = -INFINITY;
                }
            }

            // packed fp16 row-max across the 4 lanes of each row
            float rm0 = -INFINITY, rm1 = -INFINITY;
            #pragma unroll
            for (int j = 0; j < 8; j++) {
                rm0 = fmaxf(rm0, fmaxf(s[j][0], s[j][1]));
                rm1 = fmaxf(rm1, fmaxf(s[j][2], s[j][3]));
            }
            // clamp -inf to a large-negative finite for fp16 packing
            float rm0c = fmaxf(rm0, -60000.f), rm1c = fmaxf(rm1, -60000.f);
            uint32_t rmp = h2pack(rm0c, rm1c);
            rmp = hmax2(rmp, __shfl_xor_sync(0xffffffffu, rmp, 1));
            rmp = hmax2(rmp, __shfl_xor_sync(0xffffffffu, rmp, 2));
            __half2 rmh = *(__half2*)&rmp;
            float mn0 = fmaxf(m0, __half2float(rmh.x));
            float mn1 = fmaxf(m1, __half2float(rmh.y));

            // correction factors via one f16x2 exp
            float d0 = fmaxf(m0 - mn0, -60000.f), d1 = fmaxf(m1 - mn1, -60000.f);
            uint32_t cp = ex2h2(h2pack(d0, d1));
            __half2 ch = *(__half2*)&cp;
            float c0 = __half2float(ch.x), c1 = __half2float(ch.y);
            m0 = mn0; m1 = mn1;

            uint32_t ph0[8], ph1[8];
            #pragma unroll
            for (int j = 0; j < 8; j++) {
                ph0[j] = ex2h2(h2pack(s[j][0] - m0, s[j][1] - m0));
                ph1[j] = ex2h2(h2pack(s[j][2] - m1, s[j][3] - m1));
                o[j][0] *= c0; o[j][1] *= c0;
                o[j][2] *= c1; o[j][3] *= c1;
            }
            ol[0] *= c0; ol[1] *= c0;
            ol[2] *= c1; ol[3] *= c1;

            const uint32_t ones2[2] = {0x3C003C00u, 0x3C003C00u};
            #pragma unroll
            for (int aj = 0; aj < 4; aj++) {
                uint32_t pp[4];
                pp[0] = ph0[2*aj];
                pp[1] = ph1[2*aj];
                pp[2] = ph0[2*aj+1];
                pp[3] = ph1[2*aj+1];
                mma16816(ol, pp, ones2);
                #pragma unroll
                for (int j = 0; j < 8; j++) {
                    uint32_t voff = (uint32_t)(((aj * 16 + (lane & 7) + ((lane >> 3) & 1) * 8) * AP + j * 8) * 2);
                    uint32_t vf[2];
                    ldsm_x2t(vf, sV + voff);
                    mma16816(o[j], pp, vf);
                }
            }
        }
    }

    float i0 = 1.f / ol[0], i1 = 1.f / ol[2];

    const int row0 = wrow + er;
    #pragma unroll
    for (int j = 0; j < 8; j++) {
        int dim = j * 8 + ec;
        size_t o0 = (size_t)(b * Sq + row0) * Dm + h * HDc + dim;
        size_t o1 = (size_t)(b * Sq + row0 + 8) * Dm + h * HDc + dim;
        *(uint32_t*)&AH[o0] = h2pack(o[j][0] * i0, o[j][1] * i0);
        *(uint32_t*)&AH[o1] = h2pack(o[j][2] * i1, o[j][3] * i1);
    }
}

// ---------------------------------------------------------------------------
extern "C" void kernel_launch(void* const* d_in, const int* in_sizes, int n_in,
                              void* d_out, int out_size)
{
    (void)in_sizes; (void)n_in; (void)out_size;
    const float* x  = (const float*)d_in[0];
    const float* WQ = (const float*)d_in[1];
    const float* WK = (const float*)d_in[2];
    const float* WV = (const float*)d_in[3];
    const float* WO = (const float*)d_in[4];
    float* out = (float*)d_out;

    __half *xf, *wf, *ah, *qf, *kf, *vf;
    cudaGetSymbolAddress((void**)&xf, g_Xf);
    cudaGetSymbolAddress((void**)&wf, g_Wf);
    cudaGetSymbolAddress((void**)&ah, g_AH);
    cudaGetSymbolAddress((void**)&qf, g_Qf);
    cudaGetSymbolAddress((void**)&kf, g_Kf);
    cudaGetSymbolAddress((void**)&vf, g_Vf);

    static int attrs_set = 0;
    if (!attrs_set) {
        cudaFuncSetAttribute(qkv_gemm, cudaFuncAttributeMaxDynamicSharedMemorySize, GSMEM);
        cudaFuncSetAttribute(wo_gemm,  cudaFuncAttributeMaxDynamicSharedMemorySize, GSMEM);
        cudaFuncSetAttribute(attn_mma, cudaFuncAttributeMaxDynamicSharedMemorySize, ASMEM);
        attrs_set = 1;
    }

    convx_k<<<Mtot * Dm / 4 / 256, 256>>>(x, xf);
    convw_k<<<dim3(32, 32, 4), dim3(32, 8)>>>(WQ, WK, WV, WO, wf);

    qkv_gemm<<<dim3(3 * Dm / 128, Mtot / 128), 128, GSMEM>>>(
        xf, wf, qf, kf, vf);

    attn_mma<<<dim3(Sq / 128, Hh, Bq), 256, ASMEM>>>(qf, kf, vf, ah);

    wo_gemm<<<dim3(Dm / 128, Mtot / 128), 128, GSMEM>>>(
        ah, wf + 3 * (size_t)Dm * Dm, out);
}